// round 7
// baseline (speedup 1.0000x reference)
#include <cuda_runtime.h>
#include <float.h>
#include <stdint.h>

#define N_NODES 50000
#define N_EDGES 800000
#define F 128
#define L_LAYERS 3
#define G_GROUPS 256
#define T_OUT 10
#define LF (L_LAYERS * F)   // 384

#define SCAN_BLOCKS ((N_NODES + 255) / 256)   // 196

// ---------------- scratch (device globals; no allocation allowed) ----------
__device__ __align__(16) float g_agg[N_NODES * F];
__device__ __align__(16) float g_hc[N_NODES * LF];
__device__ __align__(16) int   g_deg[N_NODES];
__device__ __align__(16) int   g_row_start[N_NODES + 1];
__device__ __align__(16) int   g_cursor[N_NODES];
__device__ __align__(16) int   g_csr_src[N_EDGES];
__device__ __align__(16) int   g_bsum[SCAN_BLOCKS];

// ---------------- CSR build -----------------------------------------------
__global__ void zero_deg_kernel() {
    int i = blockIdx.x * blockDim.x + threadIdx.x;
    if (i < N_NODES) g_deg[i] = 0;
}

__global__ void deg_kernel(const int* __restrict__ ei) {
    int e = blockIdx.x * blockDim.x + threadIdx.x;
    if (e < N_EDGES) {
        int d = ei[N_EDGES + e];
        if ((unsigned)d < N_NODES) atomicAdd(&g_deg[d], 1);
    }
}

__global__ void scan_reduce_kernel() {
    __shared__ int s[256];
    int tid = threadIdx.x;
    int idx = blockIdx.x * 256 + tid;
    s[tid] = (idx < N_NODES) ? g_deg[idx] : 0;
    __syncthreads();
#pragma unroll
    for (int off = 128; off > 0; off >>= 1) {
        if (tid < off) s[tid] += s[tid + off];
        __syncthreads();
    }
    if (tid == 0) g_bsum[blockIdx.x] = s[0];
}

__global__ void scan_bsum_kernel() {
    __shared__ int s[256];
    int tid = threadIdx.x;
    int v = (tid < SCAN_BLOCKS) ? g_bsum[tid] : 0;
    s[tid] = v;
    __syncthreads();
#pragma unroll
    for (int off = 1; off < 256; off <<= 1) {
        int t = (tid >= off) ? s[tid - off] : 0;
        __syncthreads();
        s[tid] += t;
        __syncthreads();
    }
    if (tid < SCAN_BLOCKS) g_bsum[tid] = s[tid] - v;   // exclusive
}

__global__ void scan_final_kernel() {
    __shared__ int s[256];
    int tid = threadIdx.x;
    int idx = blockIdx.x * 256 + tid;
    int v = (idx < N_NODES) ? g_deg[idx] : 0;
    s[tid] = v;
    __syncthreads();
#pragma unroll
    for (int off = 1; off < 256; off <<= 1) {
        int t = (tid >= off) ? s[tid - off] : 0;
        __syncthreads();
        s[tid] += t;
        __syncthreads();
    }
    if (idx < N_NODES) {
        int excl = g_bsum[blockIdx.x] + s[tid] - v;
        g_row_start[idx] = excl;
        g_cursor[idx] = excl;
        if (idx == N_NODES - 1) g_row_start[N_NODES] = N_EDGES;
    }
}

__global__ void fill_kernel(const int* __restrict__ ei) {
    int e = blockIdx.x * blockDim.x + threadIdx.x;
    if (e < N_EDGES) {
        int src = ei[e];
        int dst = ei[N_EDGES + e];
        if ((unsigned)src < N_NODES && (unsigned)dst < N_NODES) {
            int pos = atomicAdd(&g_cursor[dst], 1);
            g_csr_src[pos] = src;
        }
    }
}

// ---------------- per-node warp gather: agg[n] = mean_{s in N(n)} h[s] ----
__global__ void __launch_bounds__(256) gather_kernel(const float* __restrict__ x, int layer) {
    int gtid = blockIdx.x * blockDim.x + threadIdx.x;
    int node = gtid >> 5;
    int lane = gtid & 31;
    if (node >= N_NODES) return;

    const float* h;
    int stride;
    if (layer == 0) { h = x; stride = F; }
    else            { h = g_hc + (layer - 1) * F; stride = LF; }

    int start = g_row_start[node];
    int end   = g_row_start[node + 1];

    float4 acc = make_float4(0.f, 0.f, 0.f, 0.f);
    int i = start;
    for (; i + 4 <= end; i += 4) {
        int s0 = g_csr_src[i + 0];
        int s1 = g_csr_src[i + 1];
        int s2 = g_csr_src[i + 2];
        int s3 = g_csr_src[i + 3];
        float4 v0 = *reinterpret_cast<const float4*>(h + (size_t)s0 * stride + lane * 4);
        float4 v1 = *reinterpret_cast<const float4*>(h + (size_t)s1 * stride + lane * 4);
        float4 v2 = *reinterpret_cast<const float4*>(h + (size_t)s2 * stride + lane * 4);
        float4 v3 = *reinterpret_cast<const float4*>(h + (size_t)s3 * stride + lane * 4);
        acc.x += v0.x + v1.x + v2.x + v3.x;
        acc.y += v0.y + v1.y + v2.y + v3.y;
        acc.z += v0.z + v1.z + v2.z + v3.z;
        acc.w += v0.w + v1.w + v2.w + v3.w;
    }
    for (; i < end; ++i) {
        int s0 = g_csr_src[i];
        float4 v0 = *reinterpret_cast<const float4*>(h + (size_t)s0 * stride + lane * 4);
        acc.x += v0.x; acc.y += v0.y; acc.z += v0.z; acc.w += v0.w;
    }

    int d = end - start;
    float inv = d > 0 ? 1.0f / (float)d : 0.0f;
    acc.x *= inv; acc.y *= inv; acc.z *= inv; acc.w *= inv;
    *reinterpret_cast<float4*>(g_agg + (size_t)node * F + lane * 4) = acc;
}

// ---------------- TF32 tensor-core GEMM, ONE pass per launch ---------------
// pass==1 (R): hc_i  = h @ Wr^T + bl          (write)
// pass==0 (L): hc_i += agg @ Wl^T             (accumulate)
// Block tile 128x128, 8 warps, warp tile 64x32, mma.m16n8k8.tf32, BK=64.
#define BKT 64
#define ASTRIDE 68
#define BSTRIDE 136
#define A_WORDS (128 * ASTRIDE)
#define B_WORDS (BKT * BSTRIDE)
#define GEMM_SMEM_BYTES ((A_WORDS + B_WORDS) * 4)   // 69632

__device__ __forceinline__ uint32_t f2tf32(float f) {
    uint32_t u;
    asm volatile("cvt.rna.tf32.f32 %0, %1;" : "=r"(u) : "f"(f));
    return u;
}

__device__ __forceinline__ void mma_tf32(float* d,
                                         const uint32_t* a, const uint32_t* b) {
    asm volatile(
        "mma.sync.aligned.m16n8k8.row.col.f32.tf32.tf32.f32 "
        "{%0,%1,%2,%3}, {%4,%5,%6,%7}, {%8,%9}, {%0,%1,%2,%3};\n"
        : "+f"(d[0]), "+f"(d[1]), "+f"(d[2]), "+f"(d[3])
        : "r"(a[0]), "r"(a[1]), "r"(a[2]), "r"(a[3]),
          "r"(b[0]), "r"(b[1]));
}

__global__ void __launch_bounds__(256, 2) sage_gemm_pass_kernel(
    const float* __restrict__ x, int layer, int pass,
    const float* __restrict__ Wl_all, const float* __restrict__ Wr_all,
    const float* __restrict__ bl_all) {

    extern __shared__ uint32_t smem[];
    uint32_t* As = smem;
    uint32_t* Bs = smem + A_WORDS;

    const float* h;
    int strideH;
    if (layer == 0) { h = x; strideH = F; }
    else            { h = g_hc + (layer - 1) * F; strideH = LF; }

    const float* A = pass ? h : g_agg;
    int sA = pass ? strideH : F;
    const float* W = pass ? (Wr_all + layer * F * F) : (Wl_all + layer * F * F);

    int tid  = threadIdx.x;
    int warp = tid >> 5;
    int lane = tid & 31;
    int wm = warp >> 2;
    int wn = warp & 3;
    int grp = lane >> 2;
    int tg  = lane & 3;

    int row0 = blockIdx.x * 128;

    float acc[4][4][4];
#pragma unroll
    for (int mf = 0; mf < 4; ++mf)
#pragma unroll
        for (int nf = 0; nf < 4; ++nf)
#pragma unroll
            for (int r = 0; r < 4; ++r) acc[mf][nf][r] = 0.f;

    for (int k0 = 0; k0 < F; k0 += BKT) {
        __syncthreads();
#pragma unroll
        for (int i = 0; i < 8; ++i) {
            int t4 = tid + i * 256;
            int m  = t4 >> 4;
            int c4 = (t4 & 15) * 4;
            float4 v = make_float4(0.f, 0.f, 0.f, 0.f);
            int grow = row0 + m;
            if (grow < N_NODES)
                v = *reinterpret_cast<const float4*>(A + (size_t)grow * sA + k0 + c4);
            uint32_t* dstp = &As[m * ASTRIDE + c4];
            dstp[0] = f2tf32(v.x);
            dstp[1] = f2tf32(v.y);
            dstp[2] = f2tf32(v.z);
            dstp[3] = f2tf32(v.w);
        }
#pragma unroll
        for (int i = 0; i < 8; ++i) {
            int t4 = tid + i * 256;
            int j  = t4 & 127;
            int c4 = (t4 >> 7) * 4;
            float4 w = *reinterpret_cast<const float4*>(W + j * F + k0 + c4);
            Bs[(c4 + 0) * BSTRIDE + j] = f2tf32(w.x);
            Bs[(c4 + 1) * BSTRIDE + j] = f2tf32(w.y);
            Bs[(c4 + 2) * BSTRIDE + j] = f2tf32(w.z);
            Bs[(c4 + 3) * BSTRIDE + j] = f2tf32(w.w);
        }
        __syncthreads();

#pragma unroll
        for (int kk = 0; kk < BKT; kk += 8) {
            uint32_t afr[4][4], bfr[4][2];
#pragma unroll
            for (int mf = 0; mf < 4; ++mf) {
                int mr = wm * 64 + mf * 16 + grp;
                afr[mf][0] = As[mr * ASTRIDE + kk + tg];
                afr[mf][1] = As[(mr + 8) * ASTRIDE + kk + tg];
                afr[mf][2] = As[mr * ASTRIDE + kk + tg + 4];
                afr[mf][3] = As[(mr + 8) * ASTRIDE + kk + tg + 4];
            }
#pragma unroll
            for (int nf = 0; nf < 4; ++nf) {
                int nc = wn * 32 + nf * 8 + grp;
                bfr[nf][0] = Bs[(kk + tg) * BSTRIDE + nc];
                bfr[nf][1] = Bs[(kk + tg + 4) * BSTRIDE + nc];
            }
#pragma unroll
            for (int mf = 0; mf < 4; ++mf)
#pragma unroll
                for (int nf = 0; nf < 4; ++nf)
                    mma_tf32(acc[mf][nf], afr[mf], bfr[nf]);
        }
    }

    // ---- epilogue ----
    const float* bias = bl_all + layer * F;
    float* outp = g_hc + layer * F;
#pragma unroll
    for (int mf = 0; mf < 4; ++mf) {
        int r0 = row0 + wm * 64 + mf * 16 + grp;
        int r1 = r0 + 8;
#pragma unroll
        for (int nf = 0; nf < 4; ++nf) {
            int c = wn * 32 + nf * 8 + 2 * tg;
            if (pass) {   // write: + bias
                float b0 = bias[c], b1 = bias[c + 1];
                if (r0 < N_NODES) {
                    float2 o = make_float2(acc[mf][nf][0] + b0, acc[mf][nf][1] + b1);
                    *reinterpret_cast<float2*>(outp + (size_t)r0 * LF + c) = o;
                }
                if (r1 < N_NODES) {
                    float2 o = make_float2(acc[mf][nf][2] + b0, acc[mf][nf][3] + b1);
                    *reinterpret_cast<float2*>(outp + (size_t)r1 * LF + c) = o;
                }
            } else {      // accumulate
                if (r0 < N_NODES) {
                    float2* p = reinterpret_cast<float2*>(outp + (size_t)r0 * LF + c);
                    float2 o = *p;
                    o.x += acc[mf][nf][0]; o.y += acc[mf][nf][1];
                    *p = o;
                }
                if (r1 < N_NODES) {
                    float2* p = reinterpret_cast<float2*>(outp + (size_t)r1 * LF + c);
                    float2 o = *p;
                    o.x += acc[mf][nf][2]; o.y += acc[mf][nf][3];
                    *p = o;
                }
            }
        }
    }
}

// ---------------- fused pool + MLP ----------------------------------------
// Block g: segment-max over its rows -> smem, then 2-layer MLP -> out.
__global__ void pool_mlp_kernel(const int* __restrict__ batch,
                                const float* __restrict__ W1, const float* __restrict__ b1,
                                const float* __restrict__ W2, const float* __restrict__ b2,
                                float* __restrict__ out) {
    int g = blockIdx.x;
    int tid = threadIdx.x;    // 0..383

    __shared__ __align__(16) float p[LF];
    __shared__ __align__(16) float z[F];

    int lo = 0, hi = N_NODES;
    while (lo < hi) { int mid = (lo + hi) >> 1; if (batch[mid] < g) lo = mid + 1; else hi = mid; }
    int start = lo;
    hi = N_NODES;
    while (lo < hi) { int mid = (lo + hi) >> 1; if (batch[mid] < g + 1) lo = mid + 1; else hi = mid; }
    int end = lo;

    float m = -FLT_MAX;
    for (int r = start; r < end; ++r)
        m = fmaxf(m, g_hc[(size_t)r * LF + tid]);
    p[tid] = m;
    __syncthreads();

    if (tid < F) {
        float s = b1[tid];
        const float* w = W1 + tid * LF;
#pragma unroll 4
        for (int k = 0; k < LF; k += 4) {
            float4 wv = *reinterpret_cast<const float4*>(w + k);
            s += wv.x * p[k] + wv.y * p[k + 1] + wv.z * p[k + 2] + wv.w * p[k + 3];
        }
        z[tid] = fmaxf(s, 0.f);
    }
    __syncthreads();

    if (tid < T_OUT) {
        float o = b2[tid];
        const float* w2 = W2 + tid * F;
#pragma unroll 4
        for (int k = 0; k < F; k += 4) {
            float4 wv = *reinterpret_cast<const float4*>(w2 + k);
            o += wv.x * z[k] + wv.y * z[k + 1] + wv.z * z[k + 2] + wv.w * z[k + 3];
        }
        out[g * T_OUT + tid] = o;
    }
}

// ---------------- launch --------------------------------------------------
extern "C" void kernel_launch(void* const* d_in, const int* in_sizes, int n_in,
                              void* d_out, int out_size) {
    const float* x     = (const float*)d_in[0];
    const int*   ei    = (const int*)d_in[1];
    const int*   batch = (const int*)d_in[2];
    const float* Wl    = (const float*)d_in[3];
    const float* bl    = (const float*)d_in[4];
    const float* Wr    = (const float*)d_in[5];
    const float* W1    = (const float*)d_in[6];
    const float* b1    = (const float*)d_in[7];
    const float* W2    = (const float*)d_in[8];
    const float* b2    = (const float*)d_in[9];
    float* out = (float*)d_out;

    static cudaStream_t s2 = nullptr;
    static cudaEvent_t ev_fork[L_LAYERS];
    static cudaEvent_t ev_done[L_LAYERS];
    static bool init_done = false;
    if (!init_done) {
        cudaFuncSetAttribute(sage_gemm_pass_kernel,
                             cudaFuncAttributeMaxDynamicSharedMemorySize,
                             GEMM_SMEM_BYTES);
        cudaStreamCreateWithFlags(&s2, cudaStreamNonBlocking);
        for (int i = 0; i < L_LAYERS; ++i) {
            cudaEventCreateWithFlags(&ev_fork[i], cudaEventDisableTiming);
            cudaEventCreateWithFlags(&ev_done[i], cudaEventDisableTiming);
        }
        init_done = true;
    }

    // CSR build (by dst)
    zero_deg_kernel<<<(N_NODES + 255) / 256, 256>>>();
    deg_kernel<<<(N_EDGES + 255) / 256, 256>>>(ei);
    scan_reduce_kernel<<<SCAN_BLOCKS, 256>>>();
    scan_bsum_kernel<<<1, 256>>>();
    scan_final_kernel<<<SCAN_BLOCKS, 256>>>();
    fill_kernel<<<(N_EDGES + 255) / 256, 256>>>(ei);

    const int gather_blocks = (N_NODES * 32 + 255) / 256;  // 6250
    const int gemm_blocks   = (N_NODES + 127) / 128;       // 391

    for (int layer = 0; layer < L_LAYERS; ++layer) {
        // fork: gemm_r (h @ Wr^T + bl) on s2, concurrent with gather on main
        cudaEventRecord(ev_fork[layer], 0);
        cudaStreamWaitEvent(s2, ev_fork[layer], 0);
        sage_gemm_pass_kernel<<<gemm_blocks, 256, GEMM_SMEM_BYTES, s2>>>(
            x, layer, /*pass=*/1, Wl, Wr, bl);
        cudaEventRecord(ev_done[layer], s2);

        gather_kernel<<<gather_blocks, 256>>>(x, layer);

        // join, then accumulate agg @ Wl^T
        cudaStreamWaitEvent(0, ev_done[layer], 0);
        sage_gemm_pass_kernel<<<gemm_blocks, 256, GEMM_SMEM_BYTES>>>(
            x, layer, /*pass=*/0, Wl, Wr, bl);
    }

    pool_mlp_kernel<<<G_GROUPS, LF>>>(batch, W1, b1, W2, b2, out);
}

// round 8
// speedup vs baseline: 1.1640x; 1.1640x over previous
#include <cuda_runtime.h>
#include <cuda_fp16.h>
#include <float.h>
#include <stdint.h>

#define N_NODES 50000
#define N_EDGES 800000
#define F 128
#define L_LAYERS 3
#define G_GROUPS 256
#define T_OUT 10
#define LF (L_LAYERS * F)   // 384

#define SCAN_BLOCKS ((N_NODES + 255) / 256)   // 196

// ---------------- scratch (device globals; no allocation allowed) ----------
__device__ __align__(16) float  g_agg[N_NODES * F];
__device__ __align__(16) float  g_hc[N_NODES * LF];
__device__ __align__(16) __half g_hc_half[N_NODES * LF];   // fp16 mirror (layers 0-1 used)
__device__ __align__(16) __half g_x_half[N_NODES * F];     // fp16 mirror of x
__device__ __align__(16) int    g_deg[N_NODES];
__device__ __align__(16) int    g_row_start[N_NODES + 1];
__device__ __align__(16) int    g_cursor[N_NODES];
__device__ __align__(16) int    g_csr_src[N_EDGES];
__device__ __align__(16) int    g_bsum[SCAN_BLOCKS];

// ---------------- x -> fp16 mirror ----------------------------------------
__global__ void convert_x_kernel(const float* __restrict__ x) {
    int i = blockIdx.x * blockDim.x + threadIdx.x;   // one float4 per thread
    if (i < (N_NODES * F) / 4) {
        float4 v = reinterpret_cast<const float4*>(x)[i];
        __half2 h0 = __floats2half2_rn(v.x, v.y);
        __half2 h1 = __floats2half2_rn(v.z, v.w);
        uint2 packed;
        packed.x = *reinterpret_cast<uint32_t*>(&h0);
        packed.y = *reinterpret_cast<uint32_t*>(&h1);
        reinterpret_cast<uint2*>(g_x_half)[i] = packed;
    }
}

// ---------------- CSR build -----------------------------------------------
__global__ void zero_deg_kernel() {
    int i = blockIdx.x * blockDim.x + threadIdx.x;
    if (i < N_NODES) g_deg[i] = 0;
}

__global__ void deg_kernel(const int* __restrict__ ei) {
    int e = blockIdx.x * blockDim.x + threadIdx.x;
    if (e < N_EDGES) {
        int d = ei[N_EDGES + e];
        if ((unsigned)d < N_NODES) atomicAdd(&g_deg[d], 1);
    }
}

__global__ void scan_reduce_kernel() {
    __shared__ int s[256];
    int tid = threadIdx.x;
    int idx = blockIdx.x * 256 + tid;
    s[tid] = (idx < N_NODES) ? g_deg[idx] : 0;
    __syncthreads();
#pragma unroll
    for (int off = 128; off > 0; off >>= 1) {
        if (tid < off) s[tid] += s[tid + off];
        __syncthreads();
    }
    if (tid == 0) g_bsum[blockIdx.x] = s[0];
}

__global__ void scan_bsum_kernel() {
    __shared__ int s[256];
    int tid = threadIdx.x;
    int v = (tid < SCAN_BLOCKS) ? g_bsum[tid] : 0;
    s[tid] = v;
    __syncthreads();
#pragma unroll
    for (int off = 1; off < 256; off <<= 1) {
        int t = (tid >= off) ? s[tid - off] : 0;
        __syncthreads();
        s[tid] += t;
        __syncthreads();
    }
    if (tid < SCAN_BLOCKS) g_bsum[tid] = s[tid] - v;   // exclusive
}

__global__ void scan_final_kernel() {
    __shared__ int s[256];
    int tid = threadIdx.x;
    int idx = blockIdx.x * 256 + tid;
    int v = (idx < N_NODES) ? g_deg[idx] : 0;
    s[tid] = v;
    __syncthreads();
#pragma unroll
    for (int off = 1; off < 256; off <<= 1) {
        int t = (tid >= off) ? s[tid - off] : 0;
        __syncthreads();
        s[tid] += t;
        __syncthreads();
    }
    if (idx < N_NODES) {
        int excl = g_bsum[blockIdx.x] + s[tid] - v;
        g_row_start[idx] = excl;
        g_cursor[idx] = excl;
        if (idx == N_NODES - 1) g_row_start[N_NODES] = N_EDGES;
    }
}

__global__ void fill_kernel(const int* __restrict__ ei) {
    int e = blockIdx.x * blockDim.x + threadIdx.x;
    if (e < N_EDGES) {
        int src = ei[e];
        int dst = ei[N_EDGES + e];
        if ((unsigned)src < N_NODES && (unsigned)dst < N_NODES) {
            int pos = atomicAdd(&g_cursor[dst], 1);
            g_csr_src[pos] = src;
        }
    }
}

// ---------------- fp16 warp gather: agg[n] = mean_{s in N(n)} h[s] --------
// One warp per dst node; lane c owns 4 halves (8B) of the 256B fp16 row.
// Accumulation in fp32; agg written fp32.
__global__ void __launch_bounds__(256) gather_kernel(int layer) {
    int gtid = blockIdx.x * blockDim.x + threadIdx.x;
    int node = gtid >> 5;
    int lane = gtid & 31;
    if (node >= N_NODES) return;

    const __half* h;
    int stride;   // in halves
    if (layer == 0) { h = g_x_half; stride = F; }
    else            { h = g_hc_half + (layer - 1) * F; stride = LF; }

    int start = g_row_start[node];
    int end   = g_row_start[node + 1];

    float4 acc = make_float4(0.f, 0.f, 0.f, 0.f);

    int i = start;
    for (; i + 4 <= end; i += 4) {
        int s0 = g_csr_src[i + 0];
        int s1 = g_csr_src[i + 1];
        int s2 = g_csr_src[i + 2];
        int s3 = g_csr_src[i + 3];
        uint2 u0 = *reinterpret_cast<const uint2*>(h + (size_t)s0 * stride + lane * 4);
        uint2 u1 = *reinterpret_cast<const uint2*>(h + (size_t)s1 * stride + lane * 4);
        uint2 u2 = *reinterpret_cast<const uint2*>(h + (size_t)s2 * stride + lane * 4);
        uint2 u3 = *reinterpret_cast<const uint2*>(h + (size_t)s3 * stride + lane * 4);
#pragma unroll
        for (int j = 0; j < 4; ++j) {
            uint2 u = (j == 0) ? u0 : (j == 1) ? u1 : (j == 2) ? u2 : u3;
            float2 f0 = __half22float2(*reinterpret_cast<__half2*>(&u.x));
            float2 f1 = __half22float2(*reinterpret_cast<__half2*>(&u.y));
            acc.x += f0.x; acc.y += f0.y; acc.z += f1.x; acc.w += f1.y;
        }
    }
    for (; i < end; ++i) {
        int s0 = g_csr_src[i];
        uint2 u = *reinterpret_cast<const uint2*>(h + (size_t)s0 * stride + lane * 4);
        float2 f0 = __half22float2(*reinterpret_cast<__half2*>(&u.x));
        float2 f1 = __half22float2(*reinterpret_cast<__half2*>(&u.y));
        acc.x += f0.x; acc.y += f0.y; acc.z += f1.x; acc.w += f1.y;
    }

    int d = end - start;
    float inv = d > 0 ? 1.0f / (float)d : 0.0f;
    acc.x *= inv; acc.y *= inv; acc.z *= inv; acc.w *= inv;
    *reinterpret_cast<float4*>(g_agg + (size_t)node * F + lane * 4) = acc;
}

// ---------------- TF32 tensor-core fused SAGE GEMM (BK=64, dyn smem) -------
// out[n,:] = agg[n,:] @ Wl^T + h[n,:] @ Wr^T + bl  (both passes in one kernel)
// Epilogue also writes fp16 mirror for layers 0-1 (next layer's gather).
#define BKT 64
#define ASTRIDE 68
#define BSTRIDE 136
#define A_WORDS (128 * ASTRIDE)
#define B_WORDS (BKT * BSTRIDE)
#define GEMM_SMEM_BYTES ((A_WORDS + B_WORDS) * 4)   // 69632

__device__ __forceinline__ uint32_t f2tf32(float f) {
    uint32_t u;
    asm volatile("cvt.rna.tf32.f32 %0, %1;" : "=r"(u) : "f"(f));
    return u;
}

__device__ __forceinline__ void mma_tf32(float* d,
                                         const uint32_t* a, const uint32_t* b) {
    asm volatile(
        "mma.sync.aligned.m16n8k8.row.col.f32.tf32.tf32.f32 "
        "{%0,%1,%2,%3}, {%4,%5,%6,%7}, {%8,%9}, {%0,%1,%2,%3};\n"
        : "+f"(d[0]), "+f"(d[1]), "+f"(d[2]), "+f"(d[3])
        : "r"(a[0]), "r"(a[1]), "r"(a[2]), "r"(a[3]),
          "r"(b[0]), "r"(b[1]));
}

__global__ void __launch_bounds__(256, 2) sage_gemm_tf32_kernel(
    const float* __restrict__ x, int layer,
    const float* __restrict__ Wl_all, const float* __restrict__ Wr_all,
    const float* __restrict__ bl_all) {

    extern __shared__ uint32_t smem[];
    uint32_t* As = smem;
    uint32_t* Bs = smem + A_WORDS;

    const float* Wl = Wl_all + layer * F * F;
    const float* Wr = Wr_all + layer * F * F;

    const float* h;
    int strideH;
    if (layer == 0) { h = x; strideH = F; }
    else            { h = g_hc + (layer - 1) * F; strideH = LF; }

    int tid  = threadIdx.x;
    int warp = tid >> 5;
    int lane = tid & 31;
    int wm = warp >> 2;
    int wn = warp & 3;
    int grp = lane >> 2;
    int tg  = lane & 3;

    int row0 = blockIdx.x * 128;

    float acc[4][4][4];
#pragma unroll
    for (int mf = 0; mf < 4; ++mf)
#pragma unroll
        for (int nf = 0; nf < 4; ++nf)
#pragma unroll
            for (int r = 0; r < 4; ++r) acc[mf][nf][r] = 0.f;

    for (int pass = 0; pass < 2; ++pass) {
        const float* A = pass ? h : g_agg;
        int sA = pass ? strideH : F;
        const float* W = pass ? Wr : Wl;

        for (int k0 = 0; k0 < F; k0 += BKT) {
            __syncthreads();
#pragma unroll
            for (int i = 0; i < 8; ++i) {
                int t4 = tid + i * 256;
                int m  = t4 >> 4;
                int c4 = (t4 & 15) * 4;
                float4 v = make_float4(0.f, 0.f, 0.f, 0.f);
                int grow = row0 + m;
                if (grow < N_NODES)
                    v = *reinterpret_cast<const float4*>(A + (size_t)grow * sA + k0 + c4);
                uint32_t* dstp = &As[m * ASTRIDE + c4];
                dstp[0] = f2tf32(v.x);
                dstp[1] = f2tf32(v.y);
                dstp[2] = f2tf32(v.z);
                dstp[3] = f2tf32(v.w);
            }
#pragma unroll
            for (int i = 0; i < 8; ++i) {
                int t4 = tid + i * 256;
                int j  = t4 & 127;
                int c4 = (t4 >> 7) * 4;
                float4 w = *reinterpret_cast<const float4*>(W + j * F + k0 + c4);
                Bs[(c4 + 0) * BSTRIDE + j] = f2tf32(w.x);
                Bs[(c4 + 1) * BSTRIDE + j] = f2tf32(w.y);
                Bs[(c4 + 2) * BSTRIDE + j] = f2tf32(w.z);
                Bs[(c4 + 3) * BSTRIDE + j] = f2tf32(w.w);
            }
            __syncthreads();

#pragma unroll
            for (int kk = 0; kk < BKT; kk += 8) {
                uint32_t afr[4][4], bfr[4][2];
#pragma unroll
                for (int mf = 0; mf < 4; ++mf) {
                    int mr = wm * 64 + mf * 16 + grp;
                    afr[mf][0] = As[mr * ASTRIDE + kk + tg];
                    afr[mf][1] = As[(mr + 8) * ASTRIDE + kk + tg];
                    afr[mf][2] = As[mr * ASTRIDE + kk + tg + 4];
                    afr[mf][3] = As[(mr + 8) * ASTRIDE + kk + tg + 4];
                }
#pragma unroll
                for (int nf = 0; nf < 4; ++nf) {
                    int nc = wn * 32 + nf * 8 + grp;
                    bfr[nf][0] = Bs[(kk + tg) * BSTRIDE + nc];
                    bfr[nf][1] = Bs[(kk + tg + 4) * BSTRIDE + nc];
                }
#pragma unroll
                for (int mf = 0; mf < 4; ++mf)
#pragma unroll
                    for (int nf = 0; nf < 4; ++nf)
                        mma_tf32(acc[mf][nf], afr[mf], bfr[nf]);
            }
        }
    }

    // ---- epilogue: + bias; write fp32 hc and (layers 0-1) fp16 mirror ----
    const float* bias = bl_all + layer * F;
    float* outp = g_hc + layer * F;
    __half* outh = g_hc_half + layer * F;
    bool write_half = (layer < L_LAYERS - 1);
#pragma unroll
    for (int mf = 0; mf < 4; ++mf) {
        int r0 = row0 + wm * 64 + mf * 16 + grp;
        int r1 = r0 + 8;
#pragma unroll
        for (int nf = 0; nf < 4; ++nf) {
            int c = wn * 32 + nf * 8 + 2 * tg;
            float b0 = bias[c], b1 = bias[c + 1];
            if (r0 < N_NODES) {
                float2 o = make_float2(acc[mf][nf][0] + b0, acc[mf][nf][1] + b1);
                *reinterpret_cast<float2*>(outp + (size_t)r0 * LF + c) = o;
                if (write_half)
                    *reinterpret_cast<__half2*>(outh + (size_t)r0 * LF + c) =
                        __floats2half2_rn(o.x, o.y);
            }
            if (r1 < N_NODES) {
                float2 o = make_float2(acc[mf][nf][2] + b0, acc[mf][nf][3] + b1);
                *reinterpret_cast<float2*>(outp + (size_t)r1 * LF + c) = o;
                if (write_half)
                    *reinterpret_cast<__half2*>(outh + (size_t)r1 * LF + c) =
                        __floats2half2_rn(o.x, o.y);
            }
        }
    }
}

// ---------------- fused pool + MLP ----------------------------------------
__global__ void pool_mlp_kernel(const int* __restrict__ batch,
                                const float* __restrict__ W1, const float* __restrict__ b1,
                                const float* __restrict__ W2, const float* __restrict__ b2,
                                float* __restrict__ out) {
    int g = blockIdx.x;
    int tid = threadIdx.x;    // 0..383

    __shared__ __align__(16) float p[LF];
    __shared__ __align__(16) float z[F];

    int lo = 0, hi = N_NODES;
    while (lo < hi) { int mid = (lo + hi) >> 1; if (batch[mid] < g) lo = mid + 1; else hi = mid; }
    int start = lo;
    hi = N_NODES;
    while (lo < hi) { int mid = (lo + hi) >> 1; if (batch[mid] < g + 1) lo = mid + 1; else hi = mid; }
    int end = lo;

    float m = -FLT_MAX;
    for (int r = start; r < end; ++r)
        m = fmaxf(m, g_hc[(size_t)r * LF + tid]);
    p[tid] = m;
    __syncthreads();

    if (tid < F) {
        float s = b1[tid];
        const float* w = W1 + tid * LF;
#pragma unroll 4
        for (int k = 0; k < LF; k += 4) {
            float4 wv = *reinterpret_cast<const float4*>(w + k);
            s += wv.x * p[k] + wv.y * p[k + 1] + wv.z * p[k + 2] + wv.w * p[k + 3];
        }
        z[tid] = fmaxf(s, 0.f);
    }
    __syncthreads();

    if (tid < T_OUT) {
        float o = b2[tid];
        const float* w2 = W2 + tid * F;
#pragma unroll 4
        for (int k = 0; k < F; k += 4) {
            float4 wv = *reinterpret_cast<const float4*>(w2 + k);
            o += wv.x * z[k] + wv.y * z[k + 1] + wv.z * z[k + 2] + wv.w * z[k + 3];
        }
        out[g * T_OUT + tid] = o;
    }
}

// ---------------- launch --------------------------------------------------
extern "C" void kernel_launch(void* const* d_in, const int* in_sizes, int n_in,
                              void* d_out, int out_size) {
    const float* x     = (const float*)d_in[0];
    const int*   ei    = (const int*)d_in[1];
    const int*   batch = (const int*)d_in[2];
    const float* Wl    = (const float*)d_in[3];
    const float* bl    = (const float*)d_in[4];
    const float* Wr    = (const float*)d_in[5];
    const float* W1    = (const float*)d_in[6];
    const float* b1    = (const float*)d_in[7];
    const float* W2    = (const float*)d_in[8];
    const float* b2    = (const float*)d_in[9];
    float* out = (float*)d_out;

    static bool init_done = false;
    if (!init_done) {
        cudaFuncSetAttribute(sage_gemm_tf32_kernel,
                             cudaFuncAttributeMaxDynamicSharedMemorySize,
                             GEMM_SMEM_BYTES);
        init_done = true;
    }

    // x -> fp16 mirror
    convert_x_kernel<<<(N_NODES * F / 4 + 255) / 256, 256>>>(x);

    // CSR build (by dst)
    zero_deg_kernel<<<(N_NODES + 255) / 256, 256>>>();
    deg_kernel<<<(N_EDGES + 255) / 256, 256>>>(ei);
    scan_reduce_kernel<<<SCAN_BLOCKS, 256>>>();
    scan_bsum_kernel<<<1, 256>>>();
    scan_final_kernel<<<SCAN_BLOCKS, 256>>>();
    fill_kernel<<<(N_EDGES + 255) / 256, 256>>>(ei);

    const int gather_blocks = (N_NODES * 32 + 255) / 256;  // 6250
    const int gemm_blocks   = (N_NODES + 127) / 128;       // 391

    for (int layer = 0; layer < L_LAYERS; ++layer) {
        gather_kernel<<<gather_blocks, 256>>>(layer);
        sage_gemm_tf32_kernel<<<gemm_blocks, 256, GEMM_SMEM_BYTES>>>(x, layer, Wl, Wr, bl);
    }

    pool_mlp_kernel<<<G_GROUPS, LF>>>(batch, W1, b1, W2, b2, out);
}

// round 9
// speedup vs baseline: 1.1657x; 1.0015x over previous
#include <cuda_runtime.h>
#include <cuda_fp16.h>
#include <float.h>
#include <stdint.h>

#define N_NODES 50000
#define N_EDGES 800000
#define F 128
#define L_LAYERS 3
#define G_GROUPS 256
#define T_OUT 10
#define LF (L_LAYERS * F)   // 384

#define SCAN_BLOCKS ((N_NODES + 255) / 256)   // 196

// ---------------- scratch (device globals; no allocation allowed) ----------
__device__ __align__(16) float  g_agg[N_NODES * F];
__device__ __align__(16) float  g_hc[N_NODES * LF];
__device__ __align__(16) __half g_hc_half[N_NODES * LF];   // fp16 mirror (layers 0-1 used)
__device__ __align__(16) __half g_x_half[N_NODES * F];     // fp16 mirror of x
__device__ __align__(16) int    g_deg[N_NODES];
__device__ __align__(16) int    g_row_start[N_NODES + 1];
__device__ __align__(16) int    g_cursor[N_NODES];
__device__ __align__(16) int    g_csr_src[N_EDGES];
__device__ __align__(16) int    g_bsum[SCAN_BLOCKS];

// ---------------- launch 0: x -> fp16 mirror, fused deg zeroing ------------
__global__ void convert_x_zero_kernel(const float* __restrict__ x) {
    int i = blockIdx.x * blockDim.x + threadIdx.x;
    if (i < (N_NODES * F) / 4) {
        float4 v = reinterpret_cast<const float4*>(x)[i];
        __half2 h0 = __floats2half2_rn(v.x, v.y);
        __half2 h1 = __floats2half2_rn(v.z, v.w);
        uint2 packed;
        packed.x = *reinterpret_cast<uint32_t*>(&h0);
        packed.y = *reinterpret_cast<uint32_t*>(&h1);
        reinterpret_cast<uint2*>(g_x_half)[i] = packed;
    }
    if (i < N_NODES) g_deg[i] = 0;
}

// ---------------- launch 1: degree ----------------------------------------
__global__ void deg_kernel(const int* __restrict__ ei) {
    int e = blockIdx.x * blockDim.x + threadIdx.x;
    if (e < N_EDGES) {
        int d = ei[N_EDGES + e];
        if ((unsigned)d < N_NODES) atomicAdd(&g_deg[d], 1);
    }
}

// ---------------- launch 2: per-block degree sums -------------------------
__global__ void scan_reduce_kernel() {
    __shared__ int s[256];
    int tid = threadIdx.x;
    int idx = blockIdx.x * 256 + tid;
    s[tid] = (idx < N_NODES) ? g_deg[idx] : 0;
    __syncthreads();
#pragma unroll
    for (int off = 128; off > 0; off >>= 1) {
        if (tid < off) s[tid] += s[tid + off];
        __syncthreads();
    }
    if (tid == 0) g_bsum[blockIdx.x] = s[0];
}

// ---------------- launch 3: fused bsum-prefix + per-element scan -----------
__global__ void scan_final_kernel() {
    __shared__ int s[256];
    __shared__ int base_sh;
    int tid = threadIdx.x;

    // block-exclusive base = sum of g_bsum[0 .. blockIdx.x)
    int v2 = (tid < blockIdx.x) ? g_bsum[tid] : 0;   // SCAN_BLOCKS=196 < 256
    s[tid] = v2;
    __syncthreads();
#pragma unroll
    for (int off = 128; off > 0; off >>= 1) {
        if (tid < off) s[tid] += s[tid + off];
        __syncthreads();
    }
    if (tid == 0) base_sh = s[0];
    __syncthreads();
    int base = base_sh;
    __syncthreads();   // s[] reused below

    int idx = blockIdx.x * 256 + tid;
    int v = (idx < N_NODES) ? g_deg[idx] : 0;
    s[tid] = v;
    __syncthreads();
#pragma unroll
    for (int off = 1; off < 256; off <<= 1) {
        int t = (tid >= off) ? s[tid - off] : 0;
        __syncthreads();
        s[tid] += t;
        __syncthreads();
    }
    if (idx < N_NODES) {
        int excl = base + s[tid] - v;
        g_row_start[idx] = excl;
        g_cursor[idx] = excl;
        if (idx == N_NODES - 1) g_row_start[N_NODES] = N_EDGES;
    }
}

// ---------------- launch 4: CSR fill --------------------------------------
__global__ void fill_kernel(const int* __restrict__ ei) {
    int e = blockIdx.x * blockDim.x + threadIdx.x;
    if (e < N_EDGES) {
        int src = ei[e];
        int dst = ei[N_EDGES + e];
        if ((unsigned)src < N_NODES && (unsigned)dst < N_NODES) {
            int pos = atomicAdd(&g_cursor[dst], 1);
            g_csr_src[pos] = src;
        }
    }
}

// ---------------- launch 5: fp16 gather, 2 nodes/warp ----------------------
// 16 lanes per node; each lane owns a 16B (8-half) chunk of the 256B row.
// Accumulation fp32; agg written fp32.
__global__ void __launch_bounds__(256) gather_kernel(int layer) {
    int gtid = blockIdx.x * blockDim.x + threadIdx.x;
    int node = gtid >> 4;          // one 16-lane group per node
    int lane = gtid & 15;          // chunk id within row
    if (node >= N_NODES) return;

    const __half* h;
    int stride;   // in halves
    if (layer == 0) { h = g_x_half; stride = F; }
    else            { h = g_hc_half + (layer - 1) * F; stride = LF; }

    int start = g_row_start[node];
    int end   = g_row_start[node + 1];

    float acc[8];
#pragma unroll
    for (int j = 0; j < 8; ++j) acc[j] = 0.f;

    int i = start;
    for (; i + 4 <= end; i += 4) {
        int s0 = g_csr_src[i + 0];
        int s1 = g_csr_src[i + 1];
        int s2 = g_csr_src[i + 2];
        int s3 = g_csr_src[i + 3];
        uint4 u0 = *reinterpret_cast<const uint4*>(h + (size_t)s0 * stride + lane * 8);
        uint4 u1 = *reinterpret_cast<const uint4*>(h + (size_t)s1 * stride + lane * 8);
        uint4 u2 = *reinterpret_cast<const uint4*>(h + (size_t)s2 * stride + lane * 8);
        uint4 u3 = *reinterpret_cast<const uint4*>(h + (size_t)s3 * stride + lane * 8);
#pragma unroll
        for (int j = 0; j < 4; ++j) {
            uint4 u = (j == 0) ? u0 : (j == 1) ? u1 : (j == 2) ? u2 : u3;
            float2 f0 = __half22float2(*reinterpret_cast<__half2*>(&u.x));
            float2 f1 = __half22float2(*reinterpret_cast<__half2*>(&u.y));
            float2 f2 = __half22float2(*reinterpret_cast<__half2*>(&u.z));
            float2 f3 = __half22float2(*reinterpret_cast<__half2*>(&u.w));
            acc[0] += f0.x; acc[1] += f0.y; acc[2] += f1.x; acc[3] += f1.y;
            acc[4] += f2.x; acc[5] += f2.y; acc[6] += f3.x; acc[7] += f3.y;
        }
    }
    for (; i < end; ++i) {
        int s0 = g_csr_src[i];
        uint4 u = *reinterpret_cast<const uint4*>(h + (size_t)s0 * stride + lane * 8);
        float2 f0 = __half22float2(*reinterpret_cast<__half2*>(&u.x));
        float2 f1 = __half22float2(*reinterpret_cast<__half2*>(&u.y));
        float2 f2 = __half22float2(*reinterpret_cast<__half2*>(&u.z));
        float2 f3 = __half22float2(*reinterpret_cast<__half2*>(&u.w));
        acc[0] += f0.x; acc[1] += f0.y; acc[2] += f1.x; acc[3] += f1.y;
        acc[4] += f2.x; acc[5] += f2.y; acc[6] += f3.x; acc[7] += f3.y;
    }

    int d = end - start;
    float inv = d > 0 ? 1.0f / (float)d : 0.0f;
#pragma unroll
    for (int j = 0; j < 8; ++j) acc[j] *= inv;

    float* outp = g_agg + (size_t)node * F + lane * 8;
    *reinterpret_cast<float4*>(outp)     = make_float4(acc[0], acc[1], acc[2], acc[3]);
    *reinterpret_cast<float4*>(outp + 4) = make_float4(acc[4], acc[5], acc[6], acc[7]);
}

// ---------------- TF32 tensor-core fused SAGE GEMM (BK=64, dyn smem) -------
#define BKT 64
#define ASTRIDE 68
#define BSTRIDE 136
#define A_WORDS (128 * ASTRIDE)
#define B_WORDS (BKT * BSTRIDE)
#define GEMM_SMEM_BYTES ((A_WORDS + B_WORDS) * 4)   // 69632

__device__ __forceinline__ uint32_t f2tf32(float f) {
    uint32_t u;
    asm volatile("cvt.rna.tf32.f32 %0, %1;" : "=r"(u) : "f"(f));
    return u;
}

__device__ __forceinline__ void mma_tf32(float* d,
                                         const uint32_t* a, const uint32_t* b) {
    asm volatile(
        "mma.sync.aligned.m16n8k8.row.col.f32.tf32.tf32.f32 "
        "{%0,%1,%2,%3}, {%4,%5,%6,%7}, {%8,%9}, {%0,%1,%2,%3};\n"
        : "+f"(d[0]), "+f"(d[1]), "+f"(d[2]), "+f"(d[3])
        : "r"(a[0]), "r"(a[1]), "r"(a[2]), "r"(a[3]),
          "r"(b[0]), "r"(b[1]));
}

__global__ void __launch_bounds__(256, 2) sage_gemm_tf32_kernel(
    const float* __restrict__ x, int layer,
    const float* __restrict__ Wl_all, const float* __restrict__ Wr_all,
    const float* __restrict__ bl_all) {

    extern __shared__ uint32_t smem[];
    uint32_t* As = smem;
    uint32_t* Bs = smem + A_WORDS;

    const float* Wl = Wl_all + layer * F * F;
    const float* Wr = Wr_all + layer * F * F;

    const float* h;
    int strideH;
    if (layer == 0) { h = x; strideH = F; }
    else            { h = g_hc + (layer - 1) * F; strideH = LF; }

    int tid  = threadIdx.x;
    int warp = tid >> 5;
    int lane = tid & 31;
    int wm = warp >> 2;
    int wn = warp & 3;
    int grp = lane >> 2;
    int tg  = lane & 3;

    int row0 = blockIdx.x * 128;

    float acc[4][4][4];
#pragma unroll
    for (int mf = 0; mf < 4; ++mf)
#pragma unroll
        for (int nf = 0; nf < 4; ++nf)
#pragma unroll
            for (int r = 0; r < 4; ++r) acc[mf][nf][r] = 0.f;

    for (int pass = 0; pass < 2; ++pass) {
        const float* A = pass ? h : g_agg;
        int sA = pass ? strideH : F;
        const float* W = pass ? Wr : Wl;

        for (int k0 = 0; k0 < F; k0 += BKT) {
            __syncthreads();
#pragma unroll
            for (int i = 0; i < 8; ++i) {
                int t4 = tid + i * 256;
                int m  = t4 >> 4;
                int c4 = (t4 & 15) * 4;
                float4 v = make_float4(0.f, 0.f, 0.f, 0.f);
                int grow = row0 + m;
                if (grow < N_NODES)
                    v = *reinterpret_cast<const float4*>(A + (size_t)grow * sA + k0 + c4);
                uint32_t* dstp = &As[m * ASTRIDE + c4];
                dstp[0] = f2tf32(v.x);
                dstp[1] = f2tf32(v.y);
                dstp[2] = f2tf32(v.z);
                dstp[3] = f2tf32(v.w);
            }
#pragma unroll
            for (int i = 0; i < 8; ++i) {
                int t4 = tid + i * 256;
                int j  = t4 & 127;
                int c4 = (t4 >> 7) * 4;
                float4 w = *reinterpret_cast<const float4*>(W + j * F + k0 + c4);
                Bs[(c4 + 0) * BSTRIDE + j] = f2tf32(w.x);
                Bs[(c4 + 1) * BSTRIDE + j] = f2tf32(w.y);
                Bs[(c4 + 2) * BSTRIDE + j] = f2tf32(w.z);
                Bs[(c4 + 3) * BSTRIDE + j] = f2tf32(w.w);
            }
            __syncthreads();

#pragma unroll
            for (int kk = 0; kk < BKT; kk += 8) {
                uint32_t afr[4][4], bfr[4][2];
#pragma unroll
                for (int mf = 0; mf < 4; ++mf) {
                    int mr = wm * 64 + mf * 16 + grp;
                    afr[mf][0] = As[mr * ASTRIDE + kk + tg];
                    afr[mf][1] = As[(mr + 8) * ASTRIDE + kk + tg];
                    afr[mf][2] = As[mr * ASTRIDE + kk + tg + 4];
                    afr[mf][3] = As[(mr + 8) * ASTRIDE + kk + tg + 4];
                }
#pragma unroll
                for (int nf = 0; nf < 4; ++nf) {
                    int nc = wn * 32 + nf * 8 + grp;
                    bfr[nf][0] = Bs[(kk + tg) * BSTRIDE + nc];
                    bfr[nf][1] = Bs[(kk + tg + 4) * BSTRIDE + nc];
                }
#pragma unroll
                for (int mf = 0; mf < 4; ++mf)
#pragma unroll
                    for (int nf = 0; nf < 4; ++nf)
                        mma_tf32(acc[mf][nf], afr[mf], bfr[nf]);
            }
        }
    }

    // ---- epilogue: + bias; write fp32 hc and (layers 0-1) fp16 mirror ----
    const float* bias = bl_all + layer * F;
    float* outp = g_hc + layer * F;
    __half* outh = g_hc_half + layer * F;
    bool write_half = (layer < L_LAYERS - 1);
#pragma unroll
    for (int mf = 0; mf < 4; ++mf) {
        int r0 = row0 + wm * 64 + mf * 16 + grp;
        int r1 = r0 + 8;
#pragma unroll
        for (int nf = 0; nf < 4; ++nf) {
            int c = wn * 32 + nf * 8 + 2 * tg;
            float b0 = bias[c], b1 = bias[c + 1];
            if (r0 < N_NODES) {
                float2 o = make_float2(acc[mf][nf][0] + b0, acc[mf][nf][1] + b1);
                *reinterpret_cast<float2*>(outp + (size_t)r0 * LF + c) = o;
                if (write_half)
                    *reinterpret_cast<__half2*>(outh + (size_t)r0 * LF + c) =
                        __floats2half2_rn(o.x, o.y);
            }
            if (r1 < N_NODES) {
                float2 o = make_float2(acc[mf][nf][2] + b0, acc[mf][nf][3] + b1);
                *reinterpret_cast<float2*>(outp + (size_t)r1 * LF + c) = o;
                if (write_half)
                    *reinterpret_cast<__half2*>(outh + (size_t)r1 * LF + c) =
                        __floats2half2_rn(o.x, o.y);
            }
        }
    }
}

// ---------------- fused pool + MLP ----------------------------------------
__global__ void pool_mlp_kernel(const int* __restrict__ batch,
                                const float* __restrict__ W1, const float* __restrict__ b1,
                                const float* __restrict__ W2, const float* __restrict__ b2,
                                float* __restrict__ out) {
    int g = blockIdx.x;
    int tid = threadIdx.x;    // 0..383

    __shared__ __align__(16) float p[LF];
    __shared__ __align__(16) float z[F];

    int lo = 0, hi = N_NODES;
    while (lo < hi) { int mid = (lo + hi) >> 1; if (batch[mid] < g) lo = mid + 1; else hi = mid; }
    int start = lo;
    hi = N_NODES;
    while (lo < hi) { int mid = (lo + hi) >> 1; if (batch[mid] < g + 1) lo = mid + 1; else hi = mid; }
    int end = lo;

    float m = -FLT_MAX;
    for (int r = start; r < end; ++r)
        m = fmaxf(m, g_hc[(size_t)r * LF + tid]);
    p[tid] = m;
    __syncthreads();

    if (tid < F) {
        float s = b1[tid];
        const float* w = W1 + tid * LF;
#pragma unroll 4
        for (int k = 0; k < LF; k += 4) {
            float4 wv = *reinterpret_cast<const float4*>(w + k);
            s += wv.x * p[k] + wv.y * p[k + 1] + wv.z * p[k + 2] + wv.w * p[k + 3];
        }
        z[tid] = fmaxf(s, 0.f);
    }
    __syncthreads();

    if (tid < T_OUT) {
        float o = b2[tid];
        const float* w2 = W2 + tid * F;
#pragma unroll 4
        for (int k = 0; k < F; k += 4) {
            float4 wv = *reinterpret_cast<const float4*>(w2 + k);
            o += wv.x * z[k] + wv.y * z[k + 1] + wv.z * z[k + 2] + wv.w * z[k + 3];
        }
        out[g * T_OUT + tid] = o;
    }
}

// ---------------- launch --------------------------------------------------
extern "C" void kernel_launch(void* const* d_in, const int* in_sizes, int n_in,
                              void* d_out, int out_size) {
    const float* x     = (const float*)d_in[0];
    const int*   ei    = (const int*)d_in[1];
    const int*   batch = (const int*)d_in[2];
    const float* Wl    = (const float*)d_in[3];
    const float* bl    = (const float*)d_in[4];
    const float* Wr    = (const float*)d_in[5];
    const float* W1    = (const float*)d_in[6];
    const float* b1    = (const float*)d_in[7];
    const float* W2    = (const float*)d_in[8];
    const float* b2    = (const float*)d_in[9];
    float* out = (float*)d_out;

    static bool init_done = false;
    if (!init_done) {
        cudaFuncSetAttribute(sage_gemm_tf32_kernel,
                             cudaFuncAttributeMaxDynamicSharedMemorySize,
                             GEMM_SMEM_BYTES);
        init_done = true;
    }

    // launches 0-4: fp16 convert + CSR build
    convert_x_zero_kernel<<<(N_NODES * F / 4 + 255) / 256, 256>>>(x);   // 0
    deg_kernel<<<(N_EDGES + 255) / 256, 256>>>(ei);                      // 1
    scan_reduce_kernel<<<SCAN_BLOCKS, 256>>>();                          // 2
    scan_final_kernel<<<SCAN_BLOCKS, 256>>>();                           // 3
    fill_kernel<<<(N_EDGES + 255) / 256, 256>>>(ei);                     // 4

    const int gather_blocks = (N_NODES * 16 + 255) / 256;  // 3125
    const int gemm_blocks   = (N_NODES + 127) / 128;       // 391

    for (int layer = 0; layer < L_LAYERS; ++layer) {
        gather_kernel<<<gather_blocks, 256>>>(layer);       // launch 5 = first gather
        sage_gemm_tf32_kernel<<<gemm_blocks, 256, GEMM_SMEM_BYTES>>>(x, layer, Wl, Wr, bl);
    }

    pool_mlp_kernel<<<G_GROUPS, LF>>>(batch, W1, b1, W2, b2, out);
}

// round 10
// speedup vs baseline: 1.3555x; 1.1628x over previous
#include <cuda_runtime.h>
#include <float.h>
#include <stdint.h>

#define N_NODES 50000
#define N_EDGES 800000
#define F 128
#define L_LAYERS 3
#define G_GROUPS 256
#define T_OUT 10
#define LF (L_LAYERS * F)   // 384

#define SCAN_BLOCKS ((N_NODES + 255) / 256)   // 196

// ---------------- scratch (device globals; no allocation allowed) ----------
__device__ __align__(16) float g_agg[N_NODES * F];
__device__ __align__(16) float g_hc[N_NODES * LF];
__device__ __align__(16) int   g_deg[N_NODES];
__device__ __align__(16) int   g_row_start[N_NODES + 1];
__device__ __align__(16) int   g_cursor[N_NODES];
__device__ __align__(16) int   g_csr_src[N_EDGES];
__device__ __align__(16) int   g_bsum[SCAN_BLOCKS];

// ---------------- CSR build -----------------------------------------------
__global__ void zero_deg_kernel() {
    int i = blockIdx.x * blockDim.x + threadIdx.x;
    if (i < N_NODES) g_deg[i] = 0;
}

__global__ void deg_kernel(const int* __restrict__ ei) {
    int e = blockIdx.x * blockDim.x + threadIdx.x;
    if (e < N_EDGES) {
        int d = ei[N_EDGES + e];
        if ((unsigned)d < N_NODES) atomicAdd(&g_deg[d], 1);
    }
}

__global__ void scan_reduce_kernel() {
    __shared__ int s[256];
    int tid = threadIdx.x;
    int idx = blockIdx.x * 256 + tid;
    s[tid] = (idx < N_NODES) ? g_deg[idx] : 0;
    __syncthreads();
#pragma unroll
    for (int off = 128; off > 0; off >>= 1) {
        if (tid < off) s[tid] += s[tid + off];
        __syncthreads();
    }
    if (tid == 0) g_bsum[blockIdx.x] = s[0];
}

// fused bsum-prefix + per-element scan (SCAN_BLOCKS=196 < 256)
__global__ void scan_final_kernel() {
    __shared__ int s[256];
    __shared__ int base_sh;
    int tid = threadIdx.x;

    int v2 = (tid < blockIdx.x) ? g_bsum[tid] : 0;
    s[tid] = v2;
    __syncthreads();
#pragma unroll
    for (int off = 128; off > 0; off >>= 1) {
        if (tid < off) s[tid] += s[tid + off];
        __syncthreads();
    }
    if (tid == 0) base_sh = s[0];
    __syncthreads();
    int base = base_sh;
    __syncthreads();   // s[] reused below

    int idx = blockIdx.x * 256 + tid;
    int v = (idx < N_NODES) ? g_deg[idx] : 0;
    s[tid] = v;
    __syncthreads();
#pragma unroll
    for (int off = 1; off < 256; off <<= 1) {
        int t = (tid >= off) ? s[tid - off] : 0;
        __syncthreads();
        s[tid] += t;
        __syncthreads();
    }
    if (idx < N_NODES) {
        int excl = base + s[tid] - v;
        g_row_start[idx] = excl;
        g_cursor[idx] = excl;
        if (idx == N_NODES - 1) g_row_start[N_NODES] = N_EDGES;
    }
}

__global__ void fill_kernel(const int* __restrict__ ei) {
    int e = blockIdx.x * blockDim.x + threadIdx.x;
    if (e < N_EDGES) {
        int src = ei[e];
        int dst = ei[N_EDGES + e];
        if ((unsigned)src < N_NODES && (unsigned)dst < N_NODES) {
            int pos = atomicAdd(&g_cursor[dst], 1);
            g_csr_src[pos] = src;
        }
    }
}

// ---------------- fp32 warp gather: agg[n] = mean_{s in N(n)} h[s] --------
// One warp per dst node; lane c owns 16B chunk c of the 512B row. (R6-proven)
__global__ void __launch_bounds__(256) gather_kernel(const float* __restrict__ x, int layer) {
    int gtid = blockIdx.x * blockDim.x + threadIdx.x;
    int node = gtid >> 5;
    int lane = gtid & 31;
    if (node >= N_NODES) return;

    const float* h;
    int stride;
    if (layer == 0) { h = x; stride = F; }
    else            { h = g_hc + (layer - 1) * F; stride = LF; }

    int start = g_row_start[node];
    int end   = g_row_start[node + 1];

    float4 acc = make_float4(0.f, 0.f, 0.f, 0.f);
    int i = start;
    for (; i + 4 <= end; i += 4) {
        int s0 = g_csr_src[i + 0];
        int s1 = g_csr_src[i + 1];
        int s2 = g_csr_src[i + 2];
        int s3 = g_csr_src[i + 3];
        float4 v0 = *reinterpret_cast<const float4*>(h + (size_t)s0 * stride + lane * 4);
        float4 v1 = *reinterpret_cast<const float4*>(h + (size_t)s1 * stride + lane * 4);
        float4 v2 = *reinterpret_cast<const float4*>(h + (size_t)s2 * stride + lane * 4);
        float4 v3 = *reinterpret_cast<const float4*>(h + (size_t)s3 * stride + lane * 4);
        acc.x += v0.x + v1.x + v2.x + v3.x;
        acc.y += v0.y + v1.y + v2.y + v3.y;
        acc.z += v0.z + v1.z + v2.z + v3.z;
        acc.w += v0.w + v1.w + v2.w + v3.w;
    }
    for (; i < end; ++i) {
        int s0 = g_csr_src[i];
        float4 v0 = *reinterpret_cast<const float4*>(h + (size_t)s0 * stride + lane * 4);
        acc.x += v0.x; acc.y += v0.y; acc.z += v0.z; acc.w += v0.w;
    }

    int d = end - start;
    float inv = d > 0 ? 1.0f / (float)d : 0.0f;
    acc.x *= inv; acc.y *= inv; acc.z *= inv; acc.w *= inv;
    *reinterpret_cast<float4*>(g_agg + (size_t)node * F + lane * 4) = acc;
}

// ---------------- TF32 tensor-core fused SAGE GEMM -------------------------
// out[n,:] = agg[n,:] @ Wl^T + h[n,:] @ Wr^T + bl
// Block tile 128x128, 8 warps, warp tile 64x32, mma.m16n8k8.tf32, BK=64.
// BOTH tiles row-major in smem with stride 68 -> STS.128 staging, and
// fragment loads hit banks (4*grp + tg) mod 32 -> conflict-free.
#define BKT 64
#define TSTRIDE 68                          // words; 68*4=272B, 16B-aligned rows
#define A_WORDS (128 * TSTRIDE)             // 8704
#define B_WORDS (128 * TSTRIDE)             // 8704
#define GEMM_SMEM_BYTES ((A_WORDS + B_WORDS) * 4)   // 69632

__device__ __forceinline__ uint32_t f2tf32(float f) {
    uint32_t u;
    asm volatile("cvt.rna.tf32.f32 %0, %1;" : "=r"(u) : "f"(f));
    return u;
}

__device__ __forceinline__ void mma_tf32(float* d,
                                         const uint32_t* a, const uint32_t* b) {
    asm volatile(
        "mma.sync.aligned.m16n8k8.row.col.f32.tf32.tf32.f32 "
        "{%0,%1,%2,%3}, {%4,%5,%6,%7}, {%8,%9}, {%0,%1,%2,%3};\n"
        : "+f"(d[0]), "+f"(d[1]), "+f"(d[2]), "+f"(d[3])
        : "r"(a[0]), "r"(a[1]), "r"(a[2]), "r"(a[3]),
          "r"(b[0]), "r"(b[1]));
}

__global__ void __launch_bounds__(256, 2) sage_gemm_tf32_kernel(
    const float* __restrict__ x, int layer,
    const float* __restrict__ Wl_all, const float* __restrict__ Wr_all,
    const float* __restrict__ bl_all) {

    extern __shared__ uint32_t smem[];
    uint32_t* As = smem;             // [128][TSTRIDE]  (rows m, cols k)
    uint32_t* Bs = smem + A_WORDS;   // [128][TSTRIDE]  (rows j, cols k)

    const float* Wl = Wl_all + layer * F * F;
    const float* Wr = Wr_all + layer * F * F;

    const float* h;
    int strideH;
    if (layer == 0) { h = x; strideH = F; }
    else            { h = g_hc + (layer - 1) * F; strideH = LF; }

    int tid  = threadIdx.x;
    int warp = tid >> 5;
    int lane = tid & 31;
    int wm = warp >> 2;
    int wn = warp & 3;
    int grp = lane >> 2;
    int tg  = lane & 3;

    int row0 = blockIdx.x * 128;

    float acc[4][4][4];
#pragma unroll
    for (int mf = 0; mf < 4; ++mf)
#pragma unroll
        for (int nf = 0; nf < 4; ++nf)
#pragma unroll
            for (int r = 0; r < 4; ++r) acc[mf][nf][r] = 0.f;

    for (int pass = 0; pass < 2; ++pass) {
        const float* A = pass ? h : g_agg;
        int sA = pass ? strideH : F;
        const float* W = pass ? Wr : Wl;

        for (int k0 = 0; k0 < F; k0 += BKT) {
            __syncthreads();   // protect previous stage's frag reads
            // ---- A stage: 128 rows x 64 cols; vectorized 16B stores ----
#pragma unroll
            for (int i = 0; i < 8; ++i) {
                int t4 = tid + i * 256;          // 0..2047
                int m  = t4 >> 4;                // 0..127
                int c4 = (t4 & 15) * 4;          // 0..60
                float4 v = make_float4(0.f, 0.f, 0.f, 0.f);
                int grow = row0 + m;
                if (grow < N_NODES)
                    v = *reinterpret_cast<const float4*>(A + (size_t)grow * sA + k0 + c4);
                uint4 t;
                t.x = f2tf32(v.x); t.y = f2tf32(v.y);
                t.z = f2tf32(v.z); t.w = f2tf32(v.w);
                *reinterpret_cast<uint4*>(&As[m * TSTRIDE + c4]) = t;
            }
            // ---- B stage: 128 rows (j) x 64 cols (k); vectorized ----
#pragma unroll
            for (int i = 0; i < 8; ++i) {
                int t4 = tid + i * 256;
                int j  = t4 >> 4;                // 0..127
                int c4 = (t4 & 15) * 4;          // 0..60
                float4 w = *reinterpret_cast<const float4*>(W + j * F + k0 + c4);
                uint4 t;
                t.x = f2tf32(w.x); t.y = f2tf32(w.y);
                t.z = f2tf32(w.z); t.w = f2tf32(w.w);
                *reinterpret_cast<uint4*>(&Bs[j * TSTRIDE + c4]) = t;
            }
            __syncthreads();

#pragma unroll
            for (int kk = 0; kk < BKT; kk += 8) {
                uint32_t afr[4][4], bfr[4][2];
#pragma unroll
                for (int mf = 0; mf < 4; ++mf) {
                    int mr = wm * 64 + mf * 16 + grp;
                    afr[mf][0] = As[mr * TSTRIDE + kk + tg];
                    afr[mf][1] = As[(mr + 8) * TSTRIDE + kk + tg];
                    afr[mf][2] = As[mr * TSTRIDE + kk + tg + 4];
                    afr[mf][3] = As[(mr + 8) * TSTRIDE + kk + tg + 4];
                }
#pragma unroll
                for (int nf = 0; nf < 4; ++nf) {
                    int nc = wn * 32 + nf * 8 + grp;
                    bfr[nf][0] = Bs[nc * TSTRIDE + kk + tg];
                    bfr[nf][1] = Bs[nc * TSTRIDE + kk + tg + 4];
                }
#pragma unroll
                for (int mf = 0; mf < 4; ++mf)
#pragma unroll
                    for (int nf = 0; nf < 4; ++nf)
                        mma_tf32(acc[mf][nf], afr[mf], bfr[nf]);
            }
        }
    }

    // ---- epilogue: + bias, write hc[:, layer*F : (layer+1)*F] ----
    const float* bias = bl_all + layer * F;
    float* outp = g_hc + layer * F;
#pragma unroll
    for (int mf = 0; mf < 4; ++mf) {
        int r0 = row0 + wm * 64 + mf * 16 + grp;
        int r1 = r0 + 8;
#pragma unroll
        for (int nf = 0; nf < 4; ++nf) {
            int c = wn * 32 + nf * 8 + 2 * tg;
            float b0 = bias[c], b1 = bias[c + 1];
            if (r0 < N_NODES) {
                float2 o = make_float2(acc[mf][nf][0] + b0, acc[mf][nf][1] + b1);
                *reinterpret_cast<float2*>(outp + (size_t)r0 * LF + c) = o;
            }
            if (r1 < N_NODES) {
                float2 o = make_float2(acc[mf][nf][2] + b0, acc[mf][nf][3] + b1);
                *reinterpret_cast<float2*>(outp + (size_t)r1 * LF + c) = o;
            }
        }
    }
}

// ---------------- fused pool + MLP ----------------------------------------
__global__ void pool_mlp_kernel(const int* __restrict__ batch,
                                const float* __restrict__ W1, const float* __restrict__ b1,
                                const float* __restrict__ W2, const float* __restrict__ b2,
                                float* __restrict__ out) {
    int g = blockIdx.x;
    int tid = threadIdx.x;    // 0..383

    __shared__ __align__(16) float p[LF];
    __shared__ __align__(16) float z[F];

    int lo = 0, hi = N_NODES;
    while (lo < hi) { int mid = (lo + hi) >> 1; if (batch[mid] < g) lo = mid + 1; else hi = mid; }
    int start = lo;
    hi = N_NODES;
    while (lo < hi) { int mid = (lo + hi) >> 1; if (batch[mid] < g + 1) lo = mid + 1; else hi = mid; }
    int end = lo;

    float m = -FLT_MAX;
    for (int r = start; r < end; ++r)
        m = fmaxf(m, g_hc[(size_t)r * LF + tid]);
    p[tid] = m;
    __syncthreads();

    if (tid < F) {
        float s = b1[tid];
        const float* w = W1 + tid * LF;
#pragma unroll 4
        for (int k = 0; k < LF; k += 4) {
            float4 wv = *reinterpret_cast<const float4*>(w + k);
            s += wv.x * p[k] + wv.y * p[k + 1] + wv.z * p[k + 2] + wv.w * p[k + 3];
        }
        z[tid] = fmaxf(s, 0.f);
    }
    __syncthreads();

    if (tid < T_OUT) {
        float o = b2[tid];
        const float* w2 = W2 + tid * F;
#pragma unroll 4
        for (int k = 0; k < F; k += 4) {
            float4 wv = *reinterpret_cast<const float4*>(w2 + k);
            o += wv.x * z[k] + wv.y * z[k + 1] + wv.z * z[k + 2] + wv.w * z[k + 3];
        }
        out[g * T_OUT + tid] = o;
    }
}

// ---------------- launch --------------------------------------------------
extern "C" void kernel_launch(void* const* d_in, const int* in_sizes, int n_in,
                              void* d_out, int out_size) {
    const float* x     = (const float*)d_in[0];
    const int*   ei    = (const int*)d_in[1];
    const int*   batch = (const int*)d_in[2];
    const float* Wl    = (const float*)d_in[3];
    const float* bl    = (const float*)d_in[4];
    const float* Wr    = (const float*)d_in[5];
    const float* W1    = (const float*)d_in[6];
    const float* b1    = (const float*)d_in[7];
    const float* W2    = (const float*)d_in[8];
    const float* b2    = (const float*)d_in[9];
    float* out = (float*)d_out;

    static bool init_done = false;
    if (!init_done) {
        cudaFuncSetAttribute(sage_gemm_tf32_kernel,
                             cudaFuncAttributeMaxDynamicSharedMemorySize,
                             GEMM_SMEM_BYTES);
        init_done = true;
    }

    // CSR build
    zero_deg_kernel<<<(N_NODES + 255) / 256, 256>>>();
    deg_kernel<<<(N_EDGES + 255) / 256, 256>>>(ei);
    scan_reduce_kernel<<<SCAN_BLOCKS, 256>>>();
    scan_final_kernel<<<SCAN_BLOCKS, 256>>>();
    fill_kernel<<<(N_EDGES + 255) / 256, 256>>>(ei);

    const int gather_blocks = (N_NODES * 32 + 255) / 256;  // 6250
    const int gemm_blocks   = (N_NODES + 127) / 128;       // 391

    for (int layer = 0; layer < L_LAYERS; ++layer) {
        gather_kernel<<<gather_blocks, 256>>>(x, layer);
        sage_gemm_tf32_kernel<<<gemm_blocks, 256, GEMM_SMEM_BYTES>>>(x, layer, Wl, Wr, bl);
    }

    pool_mlp_kernel<<<G_GROUPS, LF>>>(batch, W1, b1, W2, b2, out);
}

// round 11
// speedup vs baseline: 1.4570x; 1.0749x over previous
#include <cuda_runtime.h>
#include <cuda_fp16.h>
#include <float.h>
#include <stdint.h>

#define N_NODES 50000
#define N_EDGES 800000
#define F 128
#define L_LAYERS 3
#define G_GROUPS 256
#define T_OUT 10
#define LF (L_LAYERS * F)   // 384

#define SCAN_BLOCKS ((N_NODES + 255) / 256)   // 196

// ---------------- scratch (device globals; no allocation allowed) ----------
__device__ __align__(16) float  g_agg[N_NODES * F];        // fp32, 25.6 MB
__device__ __align__(16) __half g_hc_half[N_NODES * LF];   // SOLE hc storage, 38.4 MB
__device__ __align__(16) __half g_x_half[N_NODES * F];     // fp16 mirror of x, 12.8 MB
__device__ __align__(16) int    g_deg[N_NODES];
__device__ __align__(16) int    g_row_start[N_NODES + 1];
__device__ __align__(16) int    g_cursor[N_NODES];
__device__ __align__(16) int    g_csr_src[N_EDGES];
__device__ __align__(16) int    g_bsum[SCAN_BLOCKS];

// ---------------- x -> fp16 mirror + deg zeroing ---------------------------
__global__ void convert_x_zero_kernel(const float* __restrict__ x) {
    int i = blockIdx.x * blockDim.x + threadIdx.x;
    if (i < (N_NODES * F) / 4) {
        float4 v = reinterpret_cast<const float4*>(x)[i];
        __half2 h0 = __floats2half2_rn(v.x, v.y);
        __half2 h1 = __floats2half2_rn(v.z, v.w);
        uint2 packed;
        packed.x = *reinterpret_cast<uint32_t*>(&h0);
        packed.y = *reinterpret_cast<uint32_t*>(&h1);
        reinterpret_cast<uint2*>(g_x_half)[i] = packed;
    }
    if (i < N_NODES) g_deg[i] = 0;
}

// ---------------- CSR build -----------------------------------------------
__global__ void deg_kernel(const int* __restrict__ ei) {
    int e = blockIdx.x * blockDim.x + threadIdx.x;
    if (e < N_EDGES) {
        int d = ei[N_EDGES + e];
        if ((unsigned)d < N_NODES) atomicAdd(&g_deg[d], 1);
    }
}

__global__ void scan_reduce_kernel() {
    __shared__ int s[256];
    int tid = threadIdx.x;
    int idx = blockIdx.x * 256 + tid;
    s[tid] = (idx < N_NODES) ? g_deg[idx] : 0;
    __syncthreads();
#pragma unroll
    for (int off = 128; off > 0; off >>= 1) {
        if (tid < off) s[tid] += s[tid + off];
        __syncthreads();
    }
    if (tid == 0) g_bsum[blockIdx.x] = s[0];
}

// fused bsum-prefix + per-element scan (SCAN_BLOCKS=196 < 256)
__global__ void scan_final_kernel() {
    __shared__ int s[256];
    __shared__ int base_sh;
    int tid = threadIdx.x;

    int v2 = (tid < blockIdx.x) ? g_bsum[tid] : 0;
    s[tid] = v2;
    __syncthreads();
#pragma unroll
    for (int off = 128; off > 0; off >>= 1) {
        if (tid < off) s[tid] += s[tid + off];
        __syncthreads();
    }
    if (tid == 0) base_sh = s[0];
    __syncthreads();
    int base = base_sh;
    __syncthreads();   // s[] reused below

    int idx = blockIdx.x * 256 + tid;
    int v = (idx < N_NODES) ? g_deg[idx] : 0;
    s[tid] = v;
    __syncthreads();
#pragma unroll
    for (int off = 1; off < 256; off <<= 1) {
        int t = (tid >= off) ? s[tid - off] : 0;
        __syncthreads();
        s[tid] += t;
        __syncthreads();
    }
    if (idx < N_NODES) {
        int excl = base + s[tid] - v;
        g_row_start[idx] = excl;
        g_cursor[idx] = excl;
        if (idx == N_NODES - 1) g_row_start[N_NODES] = N_EDGES;
    }
}

__global__ void fill_kernel(const int* __restrict__ ei) {
    int e = blockIdx.x * blockDim.x + threadIdx.x;
    if (e < N_EDGES) {
        int src = ei[e];
        int dst = ei[N_EDGES + e];
        if ((unsigned)src < N_NODES && (unsigned)dst < N_NODES) {
            int pos = atomicAdd(&g_cursor[dst], 1);
            g_csr_src[pos] = src;
        }
    }
}

// ---------------- fp16 gather: agg[n] = mean_{s in N(n)} h[s] -------------
// 16 lanes per node (2 nodes/warp); lane owns a 16B (8-half) chunk of the row.
// Accumulation fp32; agg written fp32.
__global__ void __launch_bounds__(256) gather_kernel(int layer) {
    int gtid = blockIdx.x * blockDim.x + threadIdx.x;
    int node = gtid >> 4;
    int lane = gtid & 15;
    if (node >= N_NODES) return;

    const __half* h;
    int stride;   // in halves
    if (layer == 0) { h = g_x_half; stride = F; }
    else            { h = g_hc_half + (layer - 1) * F; stride = LF; }

    int start = g_row_start[node];
    int end   = g_row_start[node + 1];

    float acc[8];
#pragma unroll
    for (int j = 0; j < 8; ++j) acc[j] = 0.f;

    int i = start;
    for (; i + 4 <= end; i += 4) {
        int s0 = g_csr_src[i + 0];
        int s1 = g_csr_src[i + 1];
        int s2 = g_csr_src[i + 2];
        int s3 = g_csr_src[i + 3];
        uint4 u0 = *reinterpret_cast<const uint4*>(h + (size_t)s0 * stride + lane * 8);
        uint4 u1 = *reinterpret_cast<const uint4*>(h + (size_t)s1 * stride + lane * 8);
        uint4 u2 = *reinterpret_cast<const uint4*>(h + (size_t)s2 * stride + lane * 8);
        uint4 u3 = *reinterpret_cast<const uint4*>(h + (size_t)s3 * stride + lane * 8);
#pragma unroll
        for (int j = 0; j < 4; ++j) {
            uint4 u = (j == 0) ? u0 : (j == 1) ? u1 : (j == 2) ? u2 : u3;
            float2 f0 = __half22float2(*reinterpret_cast<__half2*>(&u.x));
            float2 f1 = __half22float2(*reinterpret_cast<__half2*>(&u.y));
            float2 f2 = __half22float2(*reinterpret_cast<__half2*>(&u.z));
            float2 f3 = __half22float2(*reinterpret_cast<__half2*>(&u.w));
            acc[0] += f0.x; acc[1] += f0.y; acc[2] += f1.x; acc[3] += f1.y;
            acc[4] += f2.x; acc[5] += f2.y; acc[6] += f3.x; acc[7] += f3.y;
        }
    }
    for (; i < end; ++i) {
        int s0 = g_csr_src[i];
        uint4 u = *reinterpret_cast<const uint4*>(h + (size_t)s0 * stride + lane * 8);
        float2 f0 = __half22float2(*reinterpret_cast<__half2*>(&u.x));
        float2 f1 = __half22float2(*reinterpret_cast<__half2*>(&u.y));
        float2 f2 = __half22float2(*reinterpret_cast<__half2*>(&u.z));
        float2 f3 = __half22float2(*reinterpret_cast<__half2*>(&u.w));
        acc[0] += f0.x; acc[1] += f0.y; acc[2] += f1.x; acc[3] += f1.y;
        acc[4] += f2.x; acc[5] += f2.y; acc[6] += f3.x; acc[7] += f3.y;
    }

    int d = end - start;
    float inv = d > 0 ? 1.0f / (float)d : 0.0f;
#pragma unroll
    for (int j = 0; j < 8; ++j) acc[j] *= inv;

    float* outp = g_agg + (size_t)node * F + lane * 8;
    *reinterpret_cast<float4*>(outp)     = make_float4(acc[0], acc[1], acc[2], acc[3]);
    *reinterpret_cast<float4*>(outp + 4) = make_float4(acc[4], acc[5], acc[6], acc[7]);
}

// ---------------- TF32 tensor-core fused SAGE GEMM -------------------------
// out[n,:] = agg[n,:] @ Wl^T + h[n,:] @ Wr^T + bl
// Pass 0 A = g_agg (fp32); pass 1 A = h in fp16. Output fp16 only.
// Block tile 128x128, 8 warps, warp tile 64x32, mma.m16n8k8.tf32, BK=64.
#define BKT 64
#define TSTRIDE 68
#define A_WORDS (128 * TSTRIDE)
#define B_WORDS (128 * TSTRIDE)
#define GEMM_SMEM_BYTES ((A_WORDS + B_WORDS) * 4)   // 69632

__device__ __forceinline__ uint32_t f2tf32(float f) {
    uint32_t u;
    asm volatile("cvt.rna.tf32.f32 %0, %1;" : "=r"(u) : "f"(f));
    return u;
}

__device__ __forceinline__ void mma_tf32(float* d,
                                         const uint32_t* a, const uint32_t* b) {
    asm volatile(
        "mma.sync.aligned.m16n8k8.row.col.f32.tf32.tf32.f32 "
        "{%0,%1,%2,%3}, {%4,%5,%6,%7}, {%8,%9}, {%0,%1,%2,%3};\n"
        : "+f"(d[0]), "+f"(d[1]), "+f"(d[2]), "+f"(d[3])
        : "r"(a[0]), "r"(a[1]), "r"(a[2]), "r"(a[3]),
          "r"(b[0]), "r"(b[1]));
}

__global__ void __launch_bounds__(256, 2) sage_gemm_tf32_kernel(
    int layer,
    const float* __restrict__ Wl_all, const float* __restrict__ Wr_all,
    const float* __restrict__ bl_all) {

    extern __shared__ uint32_t smem[];
    uint32_t* As = smem;             // [128][TSTRIDE]
    uint32_t* Bs = smem + A_WORDS;   // [128][TSTRIDE]

    const float* Wl = Wl_all + layer * F * F;
    const float* Wr = Wr_all + layer * F * F;

    const __half* hh;
    int strideH;   // in halves
    if (layer == 0) { hh = g_x_half; strideH = F; }
    else            { hh = g_hc_half + (layer - 1) * F; strideH = LF; }

    int tid  = threadIdx.x;
    int warp = tid >> 5;
    int lane = tid & 31;
    int wm = warp >> 2;
    int wn = warp & 3;
    int grp = lane >> 2;
    int tg  = lane & 3;

    int row0 = blockIdx.x * 128;

    float acc[4][4][4];
#pragma unroll
    for (int mf = 0; mf < 4; ++mf)
#pragma unroll
        for (int nf = 0; nf < 4; ++nf)
#pragma unroll
            for (int r = 0; r < 4; ++r) acc[mf][nf][r] = 0.f;

    for (int pass = 0; pass < 2; ++pass) {
        const float* W = pass ? Wr : Wl;

        for (int k0 = 0; k0 < F; k0 += BKT) {
            __syncthreads();   // protect previous stage's frag reads
            if (pass == 0) {
                // ---- A stage from fp32 agg: 2048 float4 slots ----
#pragma unroll
                for (int i = 0; i < 8; ++i) {
                    int t4 = tid + i * 256;
                    int m  = t4 >> 4;
                    int c4 = (t4 & 15) * 4;
                    float4 v = make_float4(0.f, 0.f, 0.f, 0.f);
                    int grow = row0 + m;
                    if (grow < N_NODES)
                        v = *reinterpret_cast<const float4*>(g_agg + (size_t)grow * F + k0 + c4);
                    uint4 t;
                    t.x = f2tf32(v.x); t.y = f2tf32(v.y);
                    t.z = f2tf32(v.z); t.w = f2tf32(v.w);
                    *reinterpret_cast<uint4*>(&As[m * TSTRIDE + c4]) = t;
                }
            } else {
                // ---- A stage from fp16 h: 1024 uint4 slots (8 halves each) --
#pragma unroll
                for (int i = 0; i < 4; ++i) {
                    int t4 = tid + i * 256;          // 0..1023
                    int m  = t4 >> 3;                // 0..127
                    int c8 = (t4 & 7) * 8;           // 0..56
                    uint4 u = make_uint4(0, 0, 0, 0);
                    int grow = row0 + m;
                    if (grow < N_NODES)
                        u = *reinterpret_cast<const uint4*>(hh + (size_t)grow * strideH + k0 + c8);
                    float2 f0 = __half22float2(*reinterpret_cast<__half2*>(&u.x));
                    float2 f1 = __half22float2(*reinterpret_cast<__half2*>(&u.y));
                    float2 f2 = __half22float2(*reinterpret_cast<__half2*>(&u.z));
                    float2 f3 = __half22float2(*reinterpret_cast<__half2*>(&u.w));
                    uint4 t0, t1;
                    t0.x = f2tf32(f0.x); t0.y = f2tf32(f0.y);
                    t0.z = f2tf32(f1.x); t0.w = f2tf32(f1.y);
                    t1.x = f2tf32(f2.x); t1.y = f2tf32(f2.y);
                    t1.z = f2tf32(f3.x); t1.w = f2tf32(f3.y);
                    *reinterpret_cast<uint4*>(&As[m * TSTRIDE + c8])     = t0;
                    *reinterpret_cast<uint4*>(&As[m * TSTRIDE + c8 + 4]) = t1;
                }
            }
            // ---- B stage: 128 rows (j) x 64 cols (k); vectorized ----
#pragma unroll
            for (int i = 0; i < 8; ++i) {
                int t4 = tid + i * 256;
                int j  = t4 >> 4;
                int c4 = (t4 & 15) * 4;
                float4 w = *reinterpret_cast<const float4*>(W + j * F + k0 + c4);
                uint4 t;
                t.x = f2tf32(w.x); t.y = f2tf32(w.y);
                t.z = f2tf32(w.z); t.w = f2tf32(w.w);
                *reinterpret_cast<uint4*>(&Bs[j * TSTRIDE + c4]) = t;
            }
            __syncthreads();

#pragma unroll
            for (int kk = 0; kk < BKT; kk += 8) {
                uint32_t afr[4][4], bfr[4][2];
#pragma unroll
                for (int mf = 0; mf < 4; ++mf) {
                    int mr = wm * 64 + mf * 16 + grp;
                    afr[mf][0] = As[mr * TSTRIDE + kk + tg];
                    afr[mf][1] = As[(mr + 8) * TSTRIDE + kk + tg];
                    afr[mf][2] = As[mr * TSTRIDE + kk + tg + 4];
                    afr[mf][3] = As[(mr + 8) * TSTRIDE + kk + tg + 4];
                }
#pragma unroll
                for (int nf = 0; nf < 4; ++nf) {
                    int nc = wn * 32 + nf * 8 + grp;
                    bfr[nf][0] = Bs[nc * TSTRIDE + kk + tg];
                    bfr[nf][1] = Bs[nc * TSTRIDE + kk + tg + 4];
                }
#pragma unroll
                for (int mf = 0; mf < 4; ++mf)
#pragma unroll
                    for (int nf = 0; nf < 4; ++nf)
                        mma_tf32(acc[mf][nf], afr[mf], bfr[nf]);
            }
        }
    }

    // ---- epilogue: + bias, write fp16 hc slice ----
    const float* bias = bl_all + layer * F;
    __half* outh = g_hc_half + layer * F;
#pragma unroll
    for (int mf = 0; mf < 4; ++mf) {
        int r0 = row0 + wm * 64 + mf * 16 + grp;
        int r1 = r0 + 8;
#pragma unroll
        for (int nf = 0; nf < 4; ++nf) {
            int c = wn * 32 + nf * 8 + 2 * tg;
            float b0 = bias[c], b1 = bias[c + 1];
            if (r0 < N_NODES)
                *reinterpret_cast<__half2*>(outh + (size_t)r0 * LF + c) =
                    __floats2half2_rn(acc[mf][nf][0] + b0, acc[mf][nf][1] + b1);
            if (r1 < N_NODES)
                *reinterpret_cast<__half2*>(outh + (size_t)r1 * LF + c) =
                    __floats2half2_rn(acc[mf][nf][2] + b0, acc[mf][nf][3] + b1);
        }
    }
}

// ---------------- fused pool + MLP (fp16 hc input) -------------------------
__global__ void pool_mlp_kernel(const int* __restrict__ batch,
                                const float* __restrict__ W1, const float* __restrict__ b1,
                                const float* __restrict__ W2, const float* __restrict__ b2,
                                float* __restrict__ out) {
    int g = blockIdx.x;
    int tid = threadIdx.x;    // 0..383

    __shared__ __align__(16) float p[LF];
    __shared__ __align__(16) float z[F];

    int lo = 0, hi = N_NODES;
    while (lo < hi) { int mid = (lo + hi) >> 1; if (batch[mid] < g) lo = mid + 1; else hi = mid; }
    int start = lo;
    hi = N_NODES;
    while (lo < hi) { int mid = (lo + hi) >> 1; if (batch[mid] < g + 1) lo = mid + 1; else hi = mid; }
    int end = lo;

    float m = -FLT_MAX;
    for (int r = start; r < end; ++r)
        m = fmaxf(m, __half2float(g_hc_half[(size_t)r * LF + tid]));
    p[tid] = m;
    __syncthreads();

    if (tid < F) {
        float s = b1[tid];
        const float* w = W1 + tid * LF;
#pragma unroll 4
        for (int k = 0; k < LF; k += 4) {
            float4 wv = *reinterpret_cast<const float4*>(w + k);
            s += wv.x * p[k] + wv.y * p[k + 1] + wv.z * p[k + 2] + wv.w * p[k + 3];
        }
        z[tid] = fmaxf(s, 0.f);
    }
    __syncthreads();

    if (tid < T_OUT) {
        float o = b2[tid];
        const float* w2 = W2 + tid * F;
#pragma unroll 4
        for (int k = 0; k < F; k += 4) {
            float4 wv = *reinterpret_cast<const float4*>(w2 + k);
            o += wv.x * z[k] + wv.y * z[k + 1] + wv.z * z[k + 2] + wv.w * z[k + 3];
        }
        out[g * T_OUT + tid] = o;
    }
}

// ---------------- launch --------------------------------------------------
extern "C" void kernel_launch(void* const* d_in, const int* in_sizes, int n_in,
                              void* d_out, int out_size) {
    const float* x     = (const float*)d_in[0];
    const int*   ei    = (const int*)d_in[1];
    const int*   batch = (const int*)d_in[2];
    const float* Wl    = (const float*)d_in[3];
    const float* bl    = (const float*)d_in[4];
    const float* Wr    = (const float*)d_in[5];
    const float* W1    = (const float*)d_in[6];
    const float* b1    = (const float*)d_in[7];
    const float* W2    = (const float*)d_in[8];
    const float* b2    = (const float*)d_in[9];
    float* out = (float*)d_out;

    static bool init_done = false;
    if (!init_done) {
        cudaFuncSetAttribute(sage_gemm_tf32_kernel,
                             cudaFuncAttributeMaxDynamicSharedMemorySize,
                             GEMM_SMEM_BYTES);
        init_done = true;
    }

    // fp16 convert + CSR build
    convert_x_zero_kernel<<<(N_NODES * F / 4 + 255) / 256, 256>>>(x);
    deg_kernel<<<(N_EDGES + 255) / 256, 256>>>(ei);
    scan_reduce_kernel<<<SCAN_BLOCKS, 256>>>();
    scan_final_kernel<<<SCAN_BLOCKS, 256>>>();
    fill_kernel<<<(N_EDGES + 255) / 256, 256>>>(ei);

    const int gather_blocks = (N_NODES * 16 + 255) / 256;  // 3125
    const int gemm_blocks   = (N_NODES + 127) / 128;       // 391

    for (int layer = 0; layer < L_LAYERS; ++layer) {
        gather_kernel<<<gather_blocks, 256>>>(layer);
        sage_gemm_tf32_kernel<<<gemm_blocks, 256, GEMM_SMEM_BYTES>>>(layer, Wl, Wr, bl);
    }

    pool_mlp_kernel<<<G_GROUPS, LF>>>(batch, W1, b1, W2, b2, out);
}

// round 14
// speedup vs baseline: 1.7167x; 1.1783x over previous
#include <cuda_runtime.h>
#include <cuda_fp16.h>
#include <float.h>
#include <stdint.h>

#define N_NODES 50000
#define N_EDGES 800000
#define F 128
#define L_LAYERS 3
#define G_GROUPS 256
#define T_OUT 10
#define LF (L_LAYERS * F)   // 384

#define SCAN_BLOCKS ((N_NODES + 255) / 256)   // 196

// ---------------- scratch (device globals; no allocation allowed) ----------
__device__ __align__(16) __half g_agg_half[N_NODES * F];   // fp16, 12.8 MB
__device__ __align__(16) __half g_hc_half[N_NODES * LF];   // SOLE hc storage, 38.4 MB
__device__ __align__(16) __half g_x_half[N_NODES * F];     // fp16 mirror of x, 12.8 MB
__device__ __align__(16) __half g_wl_half[L_LAYERS * F * F];
__device__ __align__(16) __half g_wr_half[L_LAYERS * F * F];
__device__ __align__(16) int    g_deg[N_NODES];
__device__ __align__(16) int    g_row_start[N_NODES + 1];
__device__ __align__(16) int    g_cursor[N_NODES];
__device__ __align__(16) int    g_csr_src[N_EDGES];
__device__ __align__(16) int    g_bsum[SCAN_BLOCKS];

// ---------------- convert x & weights to fp16, zero deg --------------------
__global__ void convert_kernel(const float* __restrict__ x,
                               const float* __restrict__ Wl,
                               const float* __restrict__ Wr) {
    int i = blockIdx.x * blockDim.x + threadIdx.x;
    if (i < (N_NODES * F) / 4) {
        float4 v = reinterpret_cast<const float4*>(x)[i];
        __half2 h0 = __floats2half2_rn(v.x, v.y);
        __half2 h1 = __floats2half2_rn(v.z, v.w);
        uint2 packed;
        packed.x = *reinterpret_cast<uint32_t*>(&h0);
        packed.y = *reinterpret_cast<uint32_t*>(&h1);
        reinterpret_cast<uint2*>(g_x_half)[i] = packed;
    }
    if (i < (L_LAYERS * F * F) / 4) {
        float4 v = reinterpret_cast<const float4*>(Wl)[i];
        __half2 h0 = __floats2half2_rn(v.x, v.y);
        __half2 h1 = __floats2half2_rn(v.z, v.w);
        uint2 p;
        p.x = *reinterpret_cast<uint32_t*>(&h0);
        p.y = *reinterpret_cast<uint32_t*>(&h1);
        reinterpret_cast<uint2*>(g_wl_half)[i] = p;

        float4 w = reinterpret_cast<const float4*>(Wr)[i];
        __half2 g0 = __floats2half2_rn(w.x, w.y);
        __half2 g1 = __floats2half2_rn(w.z, w.w);
        uint2 q;
        q.x = *reinterpret_cast<uint32_t*>(&g0);
        q.y = *reinterpret_cast<uint32_t*>(&g1);
        reinterpret_cast<uint2*>(g_wr_half)[i] = q;
    }
    if (i < N_NODES) g_deg[i] = 0;
}

// ---------------- CSR build -----------------------------------------------
__global__ void deg_kernel(const int* __restrict__ ei) {
    int e = blockIdx.x * blockDim.x + threadIdx.x;
    if (e < N_EDGES) {
        int d = ei[N_EDGES + e];
        if ((unsigned)d < N_NODES) atomicAdd(&g_deg[d], 1);
    }
}

__global__ void scan_reduce_kernel() {
    __shared__ int s[256];
    int tid = threadIdx.x;
    int idx = blockIdx.x * 256 + tid;
    s[tid] = (idx < N_NODES) ? g_deg[idx] : 0;
    __syncthreads();
#pragma unroll
    for (int off = 128; off > 0; off >>= 1) {
        if (tid < off) s[tid] += s[tid + off];
        __syncthreads();
    }
    if (tid == 0) g_bsum[blockIdx.x] = s[0];
}

__global__ void scan_final_kernel() {
    __shared__ int s[256];
    __shared__ int base_sh;
    int tid = threadIdx.x;

    int v2 = (tid < blockIdx.x) ? g_bsum[tid] : 0;
    s[tid] = v2;
    __syncthreads();
#pragma unroll
    for (int off = 128; off > 0; off >>= 1) {
        if (tid < off) s[tid] += s[tid + off];
        __syncthreads();
    }
    if (tid == 0) base_sh = s[0];
    __syncthreads();
    int base = base_sh;
    __syncthreads();   // s[] reused below

    int idx = blockIdx.x * 256 + tid;
    int v = (idx < N_NODES) ? g_deg[idx] : 0;
    s[tid] = v;
    __syncthreads();
#pragma unroll
    for (int off = 1; off < 256; off <<= 1) {
        int t = (tid >= off) ? s[tid - off] : 0;
        __syncthreads();
        s[tid] += t;
        __syncthreads();
    }
    if (idx < N_NODES) {
        int excl = base + s[tid] - v;
        g_row_start[idx] = excl;
        g_cursor[idx] = excl;
        if (idx == N_NODES - 1) g_row_start[N_NODES] = N_EDGES;
    }
}

__global__ void fill_kernel(const int* __restrict__ ei) {
    int e = blockIdx.x * blockDim.x + threadIdx.x;
    if (e < N_EDGES) {
        int src = ei[e];
        int dst = ei[N_EDGES + e];
        if ((unsigned)src < N_NODES && (unsigned)dst < N_NODES) {
            int pos = atomicAdd(&g_cursor[dst], 1);
            g_csr_src[pos] = src;
        }
    }
}

// ---------------- fp16 gather: agg[n] = mean_{s in N(n)} h[s] -------------
// 16 lanes per node (2 nodes/warp); lane owns a 16B (8-half) chunk of the row.
// Accumulation fp32; agg written fp16 (identical rounding to old staging path).
__global__ void __launch_bounds__(256) gather_kernel(int layer) {
    int gtid = blockIdx.x * blockDim.x + threadIdx.x;
    int node = gtid >> 4;
    int lane = gtid & 15;
    if (node >= N_NODES) return;

    const __half* h;
    int stride;   // in halves
    if (layer == 0) { h = g_x_half; stride = F; }
    else            { h = g_hc_half + (layer - 1) * F; stride = LF; }

    int start = g_row_start[node];
    int end   = g_row_start[node + 1];

    float acc[8];
#pragma unroll
    for (int j = 0; j < 8; ++j) acc[j] = 0.f;

    int i = start;
    for (; i + 4 <= end; i += 4) {
        int s0 = g_csr_src[i + 0];
        int s1 = g_csr_src[i + 1];
        int s2 = g_csr_src[i + 2];
        int s3 = g_csr_src[i + 3];
        uint4 u0 = *reinterpret_cast<const uint4*>(h + (size_t)s0 * stride + lane * 8);
        uint4 u1 = *reinterpret_cast<const uint4*>(h + (size_t)s1 * stride + lane * 8);
        uint4 u2 = *reinterpret_cast<const uint4*>(h + (size_t)s2 * stride + lane * 8);
        uint4 u3 = *reinterpret_cast<const uint4*>(h + (size_t)s3 * stride + lane * 8);
#pragma unroll
        for (int j = 0; j < 4; ++j) {
            uint4 u = (j == 0) ? u0 : (j == 1) ? u1 : (j == 2) ? u2 : u3;
            float2 f0 = __half22float2(*reinterpret_cast<__half2*>(&u.x));
            float2 f1 = __half22float2(*reinterpret_cast<__half2*>(&u.y));
            float2 f2 = __half22float2(*reinterpret_cast<__half2*>(&u.z));
            float2 f3 = __half22float2(*reinterpret_cast<__half2*>(&u.w));
            acc[0] += f0.x; acc[1] += f0.y; acc[2] += f1.x; acc[3] += f1.y;
            acc[4] += f2.x; acc[5] += f2.y; acc[6] += f3.x; acc[7] += f3.y;
        }
    }
    for (; i < end; ++i) {
        int s0 = g_csr_src[i];
        uint4 u = *reinterpret_cast<const uint4*>(h + (size_t)s0 * stride + lane * 8);
        float2 f0 = __half22float2(*reinterpret_cast<__half2*>(&u.x));
        float2 f1 = __half22float2(*reinterpret_cast<__half2*>(&u.y));
        float2 f2 = __half22float2(*reinterpret_cast<__half2*>(&u.z));
        float2 f3 = __half22float2(*reinterpret_cast<__half2*>(&u.w));
        acc[0] += f0.x; acc[1] += f0.y; acc[2] += f1.x; acc[3] += f1.y;
        acc[4] += f2.x; acc[5] += f2.y; acc[6] += f3.x; acc[7] += f3.y;
    }

    int d = end - start;
    float inv = d > 0 ? 1.0f / (float)d : 0.0f;
#pragma unroll
    for (int j = 0; j < 8; ++j) acc[j] *= inv;

    __half2 h0 = __floats2half2_rn(acc[0], acc[1]);
    __half2 h1 = __floats2half2_rn(acc[2], acc[3]);
    __half2 h2 = __floats2half2_rn(acc[4], acc[5]);
    __half2 h3 = __floats2half2_rn(acc[6], acc[7]);
    uint4 o;
    o.x = *reinterpret_cast<uint32_t*>(&h0);
    o.y = *reinterpret_cast<uint32_t*>(&h1);
    o.z = *reinterpret_cast<uint32_t*>(&h2);
    o.w = *reinterpret_cast<uint32_t*>(&h3);
    *reinterpret_cast<uint4*>(g_agg_half + (size_t)node * F + lane * 8) = o;
}

// ---------------- FP16 tensor-core fused SAGE GEMM -------------------------
// out[n,:] = agg[n,:] @ Wl^T + h[n,:] @ Wr^T + bl
// mma.m16n8k16.f32.f16.f16.f32; block 128x128, 8 warps, warp tile 64x32.
// Whole K=128 staged per pass; ALL staging is pure 16B copies (A fp16, B fp16).
// Frag loads: word bank = 4*row + tg (stride 68 words) -> conflict-free.
#define TSH 136                                 // halves per smem row (272B)
#define A_HALVES (128 * TSH)                    // 17408
#define GEMM_SMEM_BYTES (2 * A_HALVES * 2)      // 69632

__device__ __forceinline__ void mma_f16(float* d,
                                        const uint32_t* a, const uint32_t* b) {
    asm volatile(
        "mma.sync.aligned.m16n8k16.row.col.f32.f16.f16.f32 "
        "{%0,%1,%2,%3}, {%4,%5,%6,%7}, {%8,%9}, {%0,%1,%2,%3};\n"
        : "+f"(d[0]), "+f"(d[1]), "+f"(d[2]), "+f"(d[3])
        : "r"(a[0]), "r"(a[1]), "r"(a[2]), "r"(a[3]),
          "r"(b[0]), "r"(b[1]));
}

__global__ void __launch_bounds__(256, 2) sage_gemm_f16_kernel(
    int layer, const float* __restrict__ bl_all) {

    extern __shared__ __half smemh[];
    __half* As = smemh;              // [128][TSH]
    __half* Bs = smemh + A_HALVES;   // [128][TSH]

    const __half* hh;
    int strideH;   // in halves
    if (layer == 0) { hh = g_x_half; strideH = F; }
    else            { hh = g_hc_half + (layer - 1) * F; strideH = LF; }

    int tid  = threadIdx.x;
    int warp = tid >> 5;
    int lane = tid & 31;
    int wm = warp >> 2;
    int wn = warp & 3;
    int grp = lane >> 2;
    int tg  = lane & 3;

    int row0 = blockIdx.x * 128;

    float acc[4][4][4];
#pragma unroll
    for (int mf = 0; mf < 4; ++mf)
#pragma unroll
        for (int nf = 0; nf < 4; ++nf)
#pragma unroll
            for (int r = 0; r < 4; ++r) acc[mf][nf][r] = 0.f;

    for (int pass = 0; pass < 2; ++pass) {
        const __half* A_ptr = pass ? hh : g_agg_half;
        int strideA = pass ? strideH : F;
        const __half* Wh = pass ? (g_wr_half + layer * F * F)
                                : (g_wl_half + layer * F * F);

        __syncthreads();   // protect previous stage's frag reads
        // ---- A stage: pure 16B copies (2048 slots of 8 halves) ----
#pragma unroll
        for (int i = 0; i < 8; ++i) {
            int t4 = tid + i * 256;          // 0..2047
            int m  = t4 >> 4;                // 0..127
            int c8 = (t4 & 15) * 8;          // 0..120 (halves)
            uint4 u = make_uint4(0, 0, 0, 0);
            int grow = row0 + m;
            if (grow < N_NODES)
                u = *reinterpret_cast<const uint4*>(A_ptr + (size_t)grow * strideA + c8);
            *reinterpret_cast<uint4*>(&As[m * TSH + c8]) = u;
        }
        // ---- B stage: pure 16B copies ----
#pragma unroll
        for (int i = 0; i < 8; ++i) {
            int t4 = tid + i * 256;
            int j  = t4 >> 4;
            int c8 = (t4 & 15) * 8;
            uint4 u = *reinterpret_cast<const uint4*>(Wh + j * F + c8);
            *reinterpret_cast<uint4*>(&Bs[j * TSH + c8]) = u;
        }
        __syncthreads();

#pragma unroll
        for (int kk = 0; kk < F; kk += 16) {
            uint32_t afr[4][4], bfr[4][2];
#pragma unroll
            for (int mf = 0; mf < 4; ++mf) {
                int mr = wm * 64 + mf * 16 + grp;
                afr[mf][0] = *reinterpret_cast<const uint32_t*>(&As[mr * TSH + kk + 2 * tg]);
                afr[mf][1] = *reinterpret_cast<const uint32_t*>(&As[(mr + 8) * TSH + kk + 2 * tg]);
                afr[mf][2] = *reinterpret_cast<const uint32_t*>(&As[mr * TSH + kk + 2 * tg + 8]);
                afr[mf][3] = *reinterpret_cast<const uint32_t*>(&As[(mr + 8) * TSH + kk + 2 * tg + 8]);
            }
#pragma unroll
            for (int nf = 0; nf < 4; ++nf) {
                int nc = wn * 32 + nf * 8 + grp;
                bfr[nf][0] = *reinterpret_cast<const uint32_t*>(&Bs[nc * TSH + kk + 2 * tg]);
                bfr[nf][1] = *reinterpret_cast<const uint32_t*>(&Bs[nc * TSH + kk + 2 * tg + 8]);
            }
#pragma unroll
            for (int mf = 0; mf < 4; ++mf)
#pragma unroll
                for (int nf = 0; nf < 4; ++nf)
                    mma_f16(acc[mf][nf], afr[mf], bfr[nf]);
        }
    }

    // ---- epilogue: + bias, write fp16 hc slice ----
    const float* bias = bl_all + layer * F;
    __half* outh = g_hc_half + layer * F;
#pragma unroll
    for (int mf = 0; mf < 4; ++mf) {
        int r0 = row0 + wm * 64 + mf * 16 + grp;
        int r1 = r0 + 8;
#pragma unroll
        for (int nf = 0; nf < 4; ++nf) {
            int c = wn * 32 + nf * 8 + 2 * tg;
            float b0 = bias[c], b1 = bias[c + 1];
            if (r0 < N_NODES)
                *reinterpret_cast<__half2*>(outh + (size_t)r0 * LF + c) =
                    __floats2half2_rn(acc[mf][nf][0] + b0, acc[mf][nf][1] + b1);
            if (r1 < N_NODES)
                *reinterpret_cast<__half2*>(outh + (size_t)r1 * LF + c) =
                    __floats2half2_rn(acc[mf][nf][2] + b0, acc[mf][nf][3] + b1);
        }
    }
}

// ---------------- fused pool + MLP (fp16 hc input) -------------------------
__global__ void pool_mlp_kernel(const int* __restrict__ batch,
                                const float* __restrict__ W1, const float* __restrict__ b1,
                                const float* __restrict__ W2, const float* __restrict__ b2,
                                float* __restrict__ out) {
    int g = blockIdx.x;
    int tid = threadIdx.x;    // 0..383

    __shared__ __align__(16) float p[LF];
    __shared__ __align__(16) float z[F];

    int lo = 0, hi = N_NODES;
    while (lo < hi) { int mid = (lo + hi) >> 1; if (batch[mid] < g) lo = mid + 1; else hi = mid; }
    int start = lo;
    hi = N_NODES;
    while (lo < hi) { int mid = (lo + hi) >> 1; if (batch[mid] < g + 1) lo = mid + 1; else hi = mid; }
    int end = lo;

    float m = -FLT_MAX;
    for (int r = start; r < end; ++r)
        m = fmaxf(m, __half2float(g_hc_half[(size_t)r * LF + tid]));
    p[tid] = m;
    __syncthreads();

    if (tid < F) {
        float s = b1[tid];
        const float* w = W1 + tid * LF;
#pragma unroll 4
        for (int k = 0; k < LF; k += 4) {
            float4 wv = *reinterpret_cast<const float4*>(w + k);
            s += wv.x * p[k] + wv.y * p[k + 1] + wv.z * p[k + 2] + wv.w * p[k + 3];
        }
        z[tid] = fmaxf(s, 0.f);
    }
    __syncthreads();

    if (tid < T_OUT) {
        float o = b2[tid];
        const float* w2 = W2 + tid * F;
#pragma unroll 4
        for (int k = 0; k < F; k += 4) {
            float4 wv = *reinterpret_cast<const float4*>(w2 + k);
            o += wv.x * z[k] + wv.y * z[k + 1] + wv.z * z[k + 2] + wv.w * z[k + 3];
        }
        out[g * T_OUT + tid] = o;
    }
}

// ---------------- launch --------------------------------------------------
extern "C" void kernel_launch(void* const* d_in, const int* in_sizes, int n_in,
                              void* d_out, int out_size) {
    const float* x     = (const float*)d_in[0];
    const int*   ei    = (const int*)d_in[1];
    const int*   batch = (const int*)d_in[2];
    const float* Wl    = (const float*)d_in[3];
    const float* bl    = (const float*)d_in[4];
    const float* Wr    = (const float*)d_in[5];
    const float* W1    = (const float*)d_in[6];
    const float* b1    = (const float*)d_in[7];
    const float* W2    = (const float*)d_in[8];
    const float* b2    = (const float*)d_in[9];
    float* out = (float*)d_out;

    static bool init_done = false;
    if (!init_done) {
        cudaFuncSetAttribute(sage_gemm_f16_kernel,
                             cudaFuncAttributeMaxDynamicSharedMemorySize,
                             GEMM_SMEM_BYTES);
        init_done = true;
    }

    // fp16 convert (x + weights) + CSR build
    convert_kernel<<<(N_NODES * F / 4 + 255) / 256, 256>>>(x, Wl, Wr);
    deg_kernel<<<(N_EDGES + 255) / 256, 256>>>(ei);
    scan_reduce_kernel<<<SCAN_BLOCKS, 256>>>();
    scan_final_kernel<<<SCAN_BLOCKS, 256>>>();
    fill_kernel<<<(N_EDGES + 255) / 256, 256>>>(ei);

    const int gather_blocks = (N_NODES * 16 + 255) / 256;  // 3125
    const int gemm_blocks   = (N_NODES + 127) / 128;       // 391

    for (int layer = 0; layer < L_LAYERS; ++layer) {
        gather_kernel<<<gather_blocks, 256>>>(layer);
        sage_gemm_f16_kernel<<<gemm_blocks, 256, GEMM_SMEM_BYTES>>>(layer, bl);
    }

    pool_mlp_kernel<<<G_GROUPS, LF>>>(batch, W1, b1, W2, b2, out);
}